// round 1
// baseline (speedup 1.0000x reference)
#include <cuda_runtime.h>
#include <cuda_bf16.h>

// ---------------------------------------------------------------------------
// ShiftedWindowAttention  (Swin window-MSA)
//   B_=4096 windows, N=49 tokens, C=256, H=8 heads, hd=32
//   Stage 1: qkv = x @ qkv_w^T + qkv_b        (200704x256 @ 256x768)
//   Stage 2: per-window attention (softmax(q k^T * scale + rpe_bias + mask) v)
//   Stage 3: out = ctx @ out_w^T + out_b      (200704x256 @ 256x256)
// ---------------------------------------------------------------------------

#define NWIN    4096
#define NTOK    49
#define CDIM    256
#define HEADS_N 8
#define HD      32
#define MROWS   (NWIN * NTOK)    // 200704
#define N3      (3 * CDIM)       // 768

// Scratch (device globals: allocation-free per harness rules)
__device__ float g_qkv[(size_t)MROWS * N3];   // (M, 768) row-major
__device__ float g_ctx[(size_t)MROWS * CDIM]; // (M, 256) row-major, col = h*32+d

// ---------------------------------------------------------------------------
// Tiled SGEMM:  Out[m,n] = sum_k A[m,k] * W[n,k] + bias[n]
// Block tile 128x64, BK=32, 256 threads, 8x4 per-thread microtile.
// M % 128 == 0, N % 64 == 0, K % 32 == 0 (all true here).
// ---------------------------------------------------------------------------
__device__ __forceinline__ void sgemm_128x64(
    const float* __restrict__ A, const float* __restrict__ W,
    const float* __restrict__ bias, float* __restrict__ Out,
    int K, int N)
{
    __shared__ float As[32][128];
    __shared__ float Bs[32][64];

    const int tid  = threadIdx.x;
    const int m0   = blockIdx.y * 128;
    const int n0   = blockIdx.x * 64;
    const float* Ab = A + (size_t)m0 * K;
    const float* Wb = W + (size_t)n0 * K;
    const int trow = (tid >> 4) << 3;   // 0..120 step 8
    const int tcol = (tid & 15) << 2;   // 0..60  step 4

    float acc[8][4];
#pragma unroll
    for (int i = 0; i < 8; i++)
#pragma unroll
        for (int j = 0; j < 4; j++) acc[i][j] = 0.f;

    for (int k0 = 0; k0 < K; k0 += 32) {
        // A tile: 128 rows x 32 k, transposed into As[k][m]
#pragma unroll
        for (int i = 0; i < 4; i++) {
            int f   = tid + i * 256;        // float4 index, 0..1023
            int row = f >> 3;               // 0..127
            int c4  = (f & 7) << 2;         // 0,4,...,28
            float4 v = *reinterpret_cast<const float4*>(Ab + (size_t)row * K + k0 + c4);
            As[c4 + 0][row] = v.x; As[c4 + 1][row] = v.y;
            As[c4 + 2][row] = v.z; As[c4 + 3][row] = v.w;
        }
        // B tile: 64 n-rows x 32 k, transposed into Bs[k][n]
#pragma unroll
        for (int i = 0; i < 2; i++) {
            int f  = tid + i * 256;         // 0..511
            int n  = f >> 3;                // 0..63
            int c4 = (f & 7) << 2;
            float4 v = *reinterpret_cast<const float4*>(Wb + (size_t)n * K + k0 + c4);
            Bs[c4 + 0][n] = v.x; Bs[c4 + 1][n] = v.y;
            Bs[c4 + 2][n] = v.z; Bs[c4 + 3][n] = v.w;
        }
        __syncthreads();

#pragma unroll
        for (int k = 0; k < 32; k++) {
            float4 a0 = *reinterpret_cast<const float4*>(&As[k][trow]);
            float4 a1 = *reinterpret_cast<const float4*>(&As[k][trow + 4]);
            float4 b0 = *reinterpret_cast<const float4*>(&Bs[k][tcol]);
            float a[8] = {a0.x, a0.y, a0.z, a0.w, a1.x, a1.y, a1.z, a1.w};
            float b[4] = {b0.x, b0.y, b0.z, b0.w};
#pragma unroll
            for (int i = 0; i < 8; i++)
#pragma unroll
                for (int j = 0; j < 4; j++)
                    acc[i][j] = fmaf(a[i], b[j], acc[i][j]);
        }
        __syncthreads();
    }

    float4 bv = *reinterpret_cast<const float4*>(bias + n0 + tcol);
#pragma unroll
    for (int i = 0; i < 8; i++) {
        float4 o;
        o.x = acc[i][0] + bv.x;
        o.y = acc[i][1] + bv.y;
        o.z = acc[i][2] + bv.z;
        o.w = acc[i][3] + bv.w;
        *reinterpret_cast<float4*>(&Out[(size_t)(m0 + trow + i) * N + n0 + tcol]) = o;
    }
}

__global__ void __launch_bounds__(256) qkv_gemm_kernel(
    const float* __restrict__ x, const float* __restrict__ qkv_w,
    const float* __restrict__ qkv_b)
{
    sgemm_128x64(x, qkv_w, qkv_b, g_qkv, CDIM, N3);
}

__global__ void __launch_bounds__(256) out_gemm_kernel(
    const float* __restrict__ out_w, const float* __restrict__ out_b,
    float* __restrict__ out)
{
    sgemm_128x64(g_ctx, out_w, out_b, out, CDIM, CDIM);
}

// ---------------------------------------------------------------------------
// Per-window attention. One CTA per window, loops over 8 heads.
// k stored d-major with pad 52 in smem -> conflict-free dot-product loads.
// ---------------------------------------------------------------------------
__global__ void __launch_bounds__(256) win_attn_kernel(
    const float* __restrict__ mask, const float* __restrict__ rpe,
    const int* __restrict__ rel_index)
{
    __shared__ float sq[NTOK * HD];    // [n][d], q pre-scaled
    __shared__ float skT[HD * 52];     // [d][m], pad 52 (odd vs 32 banks)
    __shared__ float sv[NTOK * HD];    // [m][d]
    __shared__ float sp[NTOK * 50];    // logits -> probs, row stride 50
    __shared__ float smb[NTOK * 50];   // mask + rpe bias, row stride 50

    const int w    = blockIdx.x;
    const int tid  = threadIdx.x;
    const int lane = tid & 31;
    const int warp = tid >> 5;
    const float scale = 0.1767766952966369f; // 32^-0.5

    const float* qb = g_qkv + (size_t)w * NTOK * N3;
    const float* mw = mask + (size_t)(w & 63) * NTOK * NTOK;

    for (int h = 0; h < HEADS_N; h++) {
        // load q (scaled), k (transposed), v for this head
        for (int idx = tid; idx < NTOK * HD; idx += 256) {
            int n = idx >> 5, d = idx & 31;
            const float* r = qb + (size_t)n * N3 + h * HD + d;
            sq[idx]         = r[0] * scale;
            skT[d * 52 + n] = r[CDIM];
            sv[idx]         = r[2 * CDIM];
        }
        // mask + relative-position bias
        for (int idx = tid; idx < NTOK * NTOK; idx += 256) {
            int n = idx / 49, m = idx - n * 49;
            smb[n * 50 + m] = mw[idx] + rpe[rel_index[idx] * HEADS_N + h];
        }
        __syncthreads();

        // logits
        for (int idx = tid; idx < NTOK * NTOK; idx += 256) {
            int n = idx / 49, m = idx - n * 49;
            float s = 0.f;
#pragma unroll
            for (int d = 0; d < HD; d++)
                s = fmaf(sq[n * HD + d], skT[d * 52 + m], s);
            sp[n * 50 + m] = s + smb[n * 50 + m];
        }
        __syncthreads();

        // softmax: one warp per row (49 cols: lane and lane+32)
        for (int n = warp; n < NTOK; n += 8) {
            float a0 = sp[n * 50 + lane];
            float a1 = (lane + 32 < NTOK) ? sp[n * 50 + lane + 32] : -1e30f;
            float mx = fmaxf(a0, a1);
#pragma unroll
            for (int o = 16; o > 0; o >>= 1)
                mx = fmaxf(mx, __shfl_xor_sync(0xffffffffu, mx, o));
            float e0 = __expf(a0 - mx);
            float e1 = (lane + 32 < NTOK) ? __expf(a1 - mx) : 0.f;
            float s = e0 + e1;
#pragma unroll
            for (int o = 16; o > 0; o >>= 1)
                s += __shfl_xor_sync(0xffffffffu, s, o);
            float inv = 1.f / s;
            sp[n * 50 + lane] = e0 * inv;
            if (lane + 32 < NTOK) sp[n * 50 + lane + 32] = e1 * inv;
        }
        __syncthreads();

        // ctx = probs @ v ; write to (M, 256) layout, col = h*32+d
        for (int idx = tid; idx < NTOK * HD; idx += 256) {
            int n = idx >> 5, d = idx & 31;
            float s = 0.f;
#pragma unroll
            for (int m = 0; m < NTOK; m++)
                s = fmaf(sp[n * 50 + m], sv[m * HD + d], s);
            g_ctx[((size_t)w * NTOK + n) * CDIM + h * HD + d] = s;
        }
        __syncthreads();
    }
}

// ---------------------------------------------------------------------------
extern "C" void kernel_launch(void* const* d_in, const int* in_sizes, int n_in,
                              void* d_out, int out_size)
{
    const float* x     = (const float*)d_in[0];
    const float* mask  = (const float*)d_in[1];
    const float* qkv_w = (const float*)d_in[2];
    const float* qkv_b = (const float*)d_in[3];
    const float* rpe   = (const float*)d_in[4];
    const float* out_w = (const float*)d_in[5];
    const float* out_b = (const float*)d_in[6];
    const int*   rel   = (const int*)d_in[7];
    float* out = (float*)d_out;

    dim3 g1(N3 / 64, MROWS / 128);    // 12 x 1568
    qkv_gemm_kernel<<<g1, 256>>>(x, qkv_w, qkv_b);

    win_attn_kernel<<<NWIN, 256>>>(mask, rpe, rel);

    dim3 g3(CDIM / 64, MROWS / 128);  // 4 x 1568
    out_gemm_kernel<<<g3, 256>>>(out_w, out_b, out);
}

// round 2
// speedup vs baseline: 2.0622x; 2.0622x over previous
#include <cuda_runtime.h>
#include <cuda_bf16.h>

// ---------------------------------------------------------------------------
// ShiftedWindowAttention (Swin window-MSA), tf32 tensor-core GEMMs
//   B_=4096 windows, N=49 tokens, C=256, H=8 heads, hd=32
// ---------------------------------------------------------------------------

#define NWIN    4096
#define NTOK    49
#define CDIM    256
#define HEADS_N 8
#define HD      32
#define MROWS   (NWIN * NTOK)    // 200704
#define N3      (3 * CDIM)       // 768

__device__ float g_qkv[(size_t)MROWS * N3];   // (M, 768) row-major
__device__ float g_ctx[(size_t)MROWS * CDIM]; // (M, 256) row-major

// ---------------------------------------------------------------------------
// tf32 helpers
// ---------------------------------------------------------------------------
__device__ __forceinline__ unsigned f2tf(float x) {
    unsigned u;
    asm("cvt.rna.tf32.f32 %0, %1;" : "=r"(u) : "f"(x));
    return u;
}

__device__ __forceinline__ void mma_tf32(float* c, const unsigned* a, const unsigned* b) {
    asm volatile(
        "mma.sync.aligned.m16n8k8.row.col.f32.tf32.tf32.f32 "
        "{%0,%1,%2,%3}, {%4,%5,%6,%7}, {%8,%9}, {%0,%1,%2,%3};"
        : "+f"(c[0]), "+f"(c[1]), "+f"(c[2]), "+f"(c[3])
        : "r"(a[0]), "r"(a[1]), "r"(a[2]), "r"(a[3]), "r"(b[0]), "r"(b[1]));
}

// ---------------------------------------------------------------------------
// tf32 GEMM:  Out[m,n] = sum_k A[m,k] * W[n,k] + bias[n]
// Block 128x64, K staged 32 at a time, 8 warps in 4(m) x 2(n) grid,
// each warp: 32x32 via 2x4 m16n8k8 mma tiles.
// ---------------------------------------------------------------------------
__device__ __forceinline__ void gemm_tf32_128x64(
    const float* __restrict__ A, const float* __restrict__ W,
    const float* __restrict__ bias, float* __restrict__ Out,
    int K, int N)
{
    __shared__ unsigned As[128][36];
    __shared__ unsigned Ws[64][36];

    const int tid  = threadIdx.x;
    const int m0   = blockIdx.y * 128;
    const int n0   = blockIdx.x * 64;
    const int warp = tid >> 5, lane = tid & 31;
    const int wm   = (warp >> 1) * 32;   // warp m-offset in tile
    const int wn   = (warp & 1) * 32;    // warp n-offset in tile
    const int qr   = lane >> 2;          // 0..7
    const int qc   = lane & 3;           // 0..3

    const float* Ab = A + (size_t)m0 * K;
    const float* Wb = W + (size_t)n0 * K;

    float acc[2][4][4];
#pragma unroll
    for (int mi = 0; mi < 2; mi++)
#pragma unroll
        for (int ni = 0; ni < 4; ni++)
#pragma unroll
            for (int j = 0; j < 4; j++) acc[mi][ni][j] = 0.f;

    for (int k0 = 0; k0 < K; k0 += 32) {
        // stage A: 128 x 32 (cvt to tf32)
#pragma unroll
        for (int i = 0; i < 4; i++) {
            int f   = tid + i * 256;       // 0..1023
            int row = f >> 3;
            int c4  = (f & 7) << 2;
            float4 v = *reinterpret_cast<const float4*>(Ab + (size_t)row * K + k0 + c4);
            As[row][c4 + 0] = f2tf(v.x); As[row][c4 + 1] = f2tf(v.y);
            As[row][c4 + 2] = f2tf(v.z); As[row][c4 + 3] = f2tf(v.w);
        }
        // stage W: 64 x 32
#pragma unroll
        for (int i = 0; i < 2; i++) {
            int f  = tid + i * 256;        // 0..511
            int n  = f >> 3;
            int c4 = (f & 7) << 2;
            float4 v = *reinterpret_cast<const float4*>(Wb + (size_t)n * K + k0 + c4);
            Ws[n][c4 + 0] = f2tf(v.x); Ws[n][c4 + 1] = f2tf(v.y);
            Ws[n][c4 + 2] = f2tf(v.z); Ws[n][c4 + 3] = f2tf(v.w);
        }
        __syncthreads();

#pragma unroll
        for (int ks = 0; ks < 32; ks += 8) {
            unsigned a[2][4];
#pragma unroll
            for (int mi = 0; mi < 2; mi++) {
                int r = wm + mi * 16;
                a[mi][0] = As[r + qr][ks + qc];
                a[mi][1] = As[r + qr + 8][ks + qc];
                a[mi][2] = As[r + qr][ks + qc + 4];
                a[mi][3] = As[r + qr + 8][ks + qc + 4];
            }
            unsigned b[4][2];
#pragma unroll
            for (int ni = 0; ni < 4; ni++) {
                int c = wn + ni * 8;
                b[ni][0] = Ws[c + qr][ks + qc];
                b[ni][1] = Ws[c + qr][ks + qc + 4];
            }
#pragma unroll
            for (int mi = 0; mi < 2; mi++)
#pragma unroll
                for (int ni = 0; ni < 4; ni++)
                    mma_tf32(acc[mi][ni], a[mi], b[ni]);
        }
        __syncthreads();
    }

    // write back + bias
#pragma unroll
    for (int mi = 0; mi < 2; mi++) {
#pragma unroll
        for (int ni = 0; ni < 4; ni++) {
            int r = m0 + wm + mi * 16 + qr;
            int c = n0 + wn + ni * 8 + qc * 2;
            float b0 = bias[c], b1 = bias[c + 1];
            float2 o0 = make_float2(acc[mi][ni][0] + b0, acc[mi][ni][1] + b1);
            float2 o1 = make_float2(acc[mi][ni][2] + b0, acc[mi][ni][3] + b1);
            *reinterpret_cast<float2*>(&Out[(size_t)r * N + c])       = o0;
            *reinterpret_cast<float2*>(&Out[(size_t)(r + 8) * N + c]) = o1;
        }
    }
}

__global__ void __launch_bounds__(256) qkv_gemm_kernel(
    const float* __restrict__ x, const float* __restrict__ qkv_w,
    const float* __restrict__ qkv_b)
{
    gemm_tf32_128x64(x, qkv_w, qkv_b, g_qkv, CDIM, N3);
}

__global__ void __launch_bounds__(256) out_gemm_kernel(
    const float* __restrict__ out_w, const float* __restrict__ out_b,
    float* __restrict__ out)
{
    gemm_tf32_128x64(g_ctx, out_w, out_b, out, CDIM, CDIM);
}

// ---------------------------------------------------------------------------
// Per-window attention. One CTA per window, loops over 8 heads.
// 2x4 register tiles + float4 smem loads -> ~3 B of LDS traffic per FMA.
// Row stride 52 everywhere (odd vs banks for skT, padding for smb/sp tiles).
// ---------------------------------------------------------------------------
#define RS 52

__global__ void __launch_bounds__(256) win_attn_kernel(
    const float* __restrict__ mask, const float* __restrict__ rpe,
    const int* __restrict__ rel_index)
{
    __shared__ float sq[NTOK * HD];     // [n][d], q pre-scaled
    __shared__ float skT[HD * RS];      // [d][m]
    __shared__ float sv[NTOK * HD];     // [m][d]
    __shared__ float sp[NTOK * RS];     // logits -> probs
    __shared__ float smb[NTOK * RS];    // mask + rpe bias

    const int w    = blockIdx.x;
    const int tid  = threadIdx.x;
    const int lane = tid & 31;
    const int warp = tid >> 5;
    const float scale = 0.1767766952966369f; // 32^-0.5

    const float* qb = g_qkv + (size_t)w * NTOK * N3;
    const float* mw = mask + (size_t)(w & 63) * NTOK * NTOK;

    for (int h = 0; h < HEADS_N; h++) {
        // load q (scaled), k (transposed), v for this head
        for (int idx = tid; idx < NTOK * HD; idx += 256) {
            int n = idx >> 5, d = idx & 31;
            const float* r = qb + (size_t)n * N3 + h * HD + d;
            sq[idx]         = r[0] * scale;
            skT[d * RS + n] = r[CDIM];
            sv[idx]         = r[2 * CDIM];
        }
        // mask + relative-position bias
        for (int idx = tid; idx < NTOK * NTOK; idx += 256) {
            int n = idx / 49, m = idx - n * 49;
            smb[n * RS + m] = mw[idx] + rpe[rel_index[idx] * HEADS_N + h];
        }
        __syncthreads();

        // logits: 2 rows x 4 cols per work item (25 x 13 tiles = 325 items)
        for (int it = tid; it < 325; it += 256) {
            int n2 = it / 13, m4 = it - n2 * 13;
            int n = n2 * 2, m = m4 * 4;
            bool row1 = (n + 1 < NTOK);
            float a0[4], a1[4];
#pragma unroll
            for (int j = 0; j < 4; j++) {
                a0[j] = smb[n * RS + m + j];
                a1[j] = row1 ? smb[(n + 1) * RS + m + j] : 0.f;
            }
#pragma unroll
            for (int d = 0; d < HD; d++) {
                float4 kk = *reinterpret_cast<const float4*>(&skT[d * RS + m]);
                float q0 = sq[n * HD + d];
                float q1 = row1 ? sq[(n + 1) * HD + d] : 0.f;
                a0[0] = fmaf(q0, kk.x, a0[0]); a0[1] = fmaf(q0, kk.y, a0[1]);
                a0[2] = fmaf(q0, kk.z, a0[2]); a0[3] = fmaf(q0, kk.w, a0[3]);
                a1[0] = fmaf(q1, kk.x, a1[0]); a1[1] = fmaf(q1, kk.y, a1[1]);
                a1[2] = fmaf(q1, kk.z, a1[2]); a1[3] = fmaf(q1, kk.w, a1[3]);
            }
            int jmax = NTOK - m; if (jmax > 4) jmax = 4;
#pragma unroll 4
            for (int j = 0; j < jmax; j++) {
                sp[n * RS + m + j] = a0[j];
                if (row1) sp[(n + 1) * RS + m + j] = a1[j];
            }
        }
        __syncthreads();

        // softmax: one warp per row
        for (int n = warp; n < NTOK; n += 8) {
            float a0 = sp[n * RS + lane];
            float a1 = (lane + 32 < NTOK) ? sp[n * RS + lane + 32] : -1e30f;
            float mx = fmaxf(a0, a1);
#pragma unroll
            for (int o = 16; o > 0; o >>= 1)
                mx = fmaxf(mx, __shfl_xor_sync(0xffffffffu, mx, o));
            float e0 = __expf(a0 - mx);
            float e1 = (lane + 32 < NTOK) ? __expf(a1 - mx) : 0.f;
            float s = e0 + e1;
#pragma unroll
            for (int o = 16; o > 0; o >>= 1)
                s += __shfl_xor_sync(0xffffffffu, s, o);
            float inv = 1.f / s;
            sp[n * RS + lane] = e0 * inv;
            if (lane + 32 < NTOK) sp[n * RS + lane + 32] = e1 * inv;
        }
        __syncthreads();

        // ctx = probs @ v : 2 rows x 4 dims per work item (25 x 8 = 200 items)
        if (tid < 200) {
            int n2 = tid >> 3, d4 = tid & 7;
            int n = n2 * 2, d = d4 * 4;
            bool row1 = (n + 1 < NTOK);
            float a0[4] = {0.f, 0.f, 0.f, 0.f};
            float a1[4] = {0.f, 0.f, 0.f, 0.f};
#pragma unroll 7
            for (int m = 0; m < NTOK; m++) {
                float4 v = *reinterpret_cast<const float4*>(&sv[m * HD + d]);
                float p0 = sp[n * RS + m];
                float p1 = row1 ? sp[(n + 1) * RS + m] : 0.f;
                a0[0] = fmaf(p0, v.x, a0[0]); a0[1] = fmaf(p0, v.y, a0[1]);
                a0[2] = fmaf(p0, v.z, a0[2]); a0[3] = fmaf(p0, v.w, a0[3]);
                a1[0] = fmaf(p1, v.x, a1[0]); a1[1] = fmaf(p1, v.y, a1[1]);
                a1[2] = fmaf(p1, v.z, a1[2]); a1[3] = fmaf(p1, v.w, a1[3]);
            }
            float* o0 = &g_ctx[((size_t)w * NTOK + n) * CDIM + h * HD + d];
            *reinterpret_cast<float4*>(o0) = make_float4(a0[0], a0[1], a0[2], a0[3]);
            if (row1)
                *reinterpret_cast<float4*>(o0 + CDIM) =
                    make_float4(a1[0], a1[1], a1[2], a1[3]);
        }
        __syncthreads();
    }
}

// ---------------------------------------------------------------------------
extern "C" void kernel_launch(void* const* d_in, const int* in_sizes, int n_in,
                              void* d_out, int out_size)
{
    const float* x     = (const float*)d_in[0];
    const float* mask  = (const float*)d_in[1];
    const float* qkv_w = (const float*)d_in[2];
    const float* qkv_b = (const float*)d_in[3];
    const float* rpe   = (const float*)d_in[4];
    const float* out_w = (const float*)d_in[5];
    const float* out_b = (const float*)d_in[6];
    const int*   rel   = (const int*)d_in[7];
    float* out = (float*)d_out;

    dim3 g1(N3 / 64, MROWS / 128);    // 12 x 1568
    qkv_gemm_kernel<<<g1, 256>>>(x, qkv_w, qkv_b);

    win_attn_kernel<<<NWIN, 256>>>(mask, rpe, rel);

    dim3 g3(CDIM / 64, MROWS / 128);  // 4 x 1568
    out_gemm_kernel<<<g3, 256>>>(out_w, out_b, out);
}

// round 3
// speedup vs baseline: 2.3208x; 1.1254x over previous
#include <cuda_runtime.h>
#include <cuda_bf16.h>
#include <cstdint>

// ---------------------------------------------------------------------------
// ShiftedWindowAttention (Swin window-MSA)
//   tf32 tensor-core GEMMs with ldmatrix + XOR-swizzled smem
//   B_=4096 windows, N=49 tokens, C=256, H=8 heads, hd=32
// ---------------------------------------------------------------------------

#define NWIN    4096
#define NTOK    49
#define CDIM    256
#define HEADS_N 8
#define HD      32
#define MROWS   (NWIN * NTOK)    // 200704
#define N3      (3 * CDIM)       // 768

__device__ float g_qkv[(size_t)MROWS * N3];   // (M, 768) row-major
__device__ float g_ctx[(size_t)MROWS * CDIM]; // (M, 256) row-major

// ---------------------------------------------------------------------------
// helpers
// ---------------------------------------------------------------------------
__device__ __forceinline__ unsigned f2tf(float x) {
    unsigned u;
    asm("cvt.rna.tf32.f32 %0, %1;" : "=r"(u) : "f"(x));
    return u;
}

__device__ __forceinline__ uint32_t s2u(const void* p) {
    return (uint32_t)__cvta_generic_to_shared(p);
}

__device__ __forceinline__ uint4 ldsm4(uint32_t a) {
    uint4 r;
    asm volatile("ldmatrix.sync.aligned.m8n8.x4.shared.b16 {%0,%1,%2,%3}, [%4];"
                 : "=r"(r.x), "=r"(r.y), "=r"(r.z), "=r"(r.w) : "r"(a));
    return r;
}

__device__ __forceinline__ void mma_tf32(float* c, const uint4& a,
                                         unsigned b0, unsigned b1) {
    asm volatile(
        "mma.sync.aligned.m16n8k8.row.col.f32.tf32.tf32.f32 "
        "{%0,%1,%2,%3}, {%4,%5,%6,%7}, {%8,%9}, {%0,%1,%2,%3};"
        : "+f"(c[0]), "+f"(c[1]), "+f"(c[2]), "+f"(c[3])
        : "r"(a.x), "r"(a.y), "r"(a.z), "r"(a.w), "r"(b0), "r"(b1));
}

// ---------------------------------------------------------------------------
// tf32 GEMM:  Out[m,n] = sum_k A[m,k] * W[n,k] + bias[n]
// Block 128x64, K staged 32 at a time, 8 warps (4m x 2n), warp tile 32x32.
// Smem: row-major, 32 words/row, 16B-slot XOR swizzle (slot ^= row&7).
// Fragments via ldmatrix.x4 (conflict-free); staging via STS.128.
// ---------------------------------------------------------------------------
__device__ __forceinline__ void gemm_tf32_128x64(
    const float* __restrict__ A, const float* __restrict__ W,
    const float* __restrict__ bias, float* __restrict__ Out,
    int K, int N)
{
    __shared__ __align__(16) unsigned As[128 * 32];
    __shared__ __align__(16) unsigned Ws[64 * 32];

    const int tid  = threadIdx.x;
    const int m0   = blockIdx.y * 128;
    const int n0   = blockIdx.x * 64;
    const int warp = tid >> 5, lane = tid & 31;
    const int qr   = lane >> 2, qc = lane & 3;
    const int wm   = (warp >> 1) * 32;
    const int wn   = (warp & 1) * 32;
    const int g    = lane >> 3;       // ldmatrix sub-matrix group
    const int r7   = lane & 7;

    const float* Ab = A + (size_t)m0 * K;
    const float* Wb = W + (size_t)n0 * K;

    // ldmatrix per-lane row addresses
    const int khA   = g >> 1;                  // A: k-high selector
    const int rowA0 = wm + (g & 1) * 8 + r7;   // A sub rows (mi=0)
    const int khB   = g & 1;                   // B: k-high selector
    const int nB0   = wn + (g >> 1) * 8 + r7;  // B sub rows (p2=0)

    const uint32_t aA0 = s2u(As) + rowA0 * 128;        // 32 words * 4B
    const uint32_t aA1 = aA0 + 16 * 128;
    const uint32_t aB0 = s2u(Ws) + nB0 * 128;
    const uint32_t aB1 = aB0 + 16 * 128;

    float acc[2][4][4];
#pragma unroll
    for (int mi = 0; mi < 2; mi++)
#pragma unroll
        for (int ni = 0; ni < 4; ni++)
#pragma unroll
            for (int j = 0; j < 4; j++) acc[mi][ni][j] = 0.f;

    for (int k0 = 0; k0 < K; k0 += 32) {
        // stage A: 128 x 32, STS.128 with XOR swizzle
#pragma unroll
        for (int i = 0; i < 4; i++) {
            int f   = tid + i * 256;       // 0..1023
            int row = f >> 3;
            int c4  = (f & 7) << 2;
            float4 v = *reinterpret_cast<const float4*>(Ab + (size_t)row * K + k0 + c4);
            uint4 t = make_uint4(f2tf(v.x), f2tf(v.y), f2tf(v.z), f2tf(v.w));
            int slot = (c4 >> 2) ^ (row & 7);
            *reinterpret_cast<uint4*>(&As[row * 32 + slot * 4]) = t;
        }
        // stage W: 64 x 32
#pragma unroll
        for (int i = 0; i < 2; i++) {
            int f  = tid + i * 256;        // 0..511
            int n  = f >> 3;
            int c4 = (f & 7) << 2;
            float4 v = *reinterpret_cast<const float4*>(Wb + (size_t)n * K + k0 + c4);
            uint4 t = make_uint4(f2tf(v.x), f2tf(v.y), f2tf(v.z), f2tf(v.w));
            int slot = (c4 >> 2) ^ (n & 7);
            *reinterpret_cast<uint4*>(&Ws[n * 32 + slot * 4]) = t;
        }
        __syncthreads();

#pragma unroll
        for (int ks = 0; ks < 4; ks++) {
            const int slA = (((2 * ks + khA) ^ r7) << 4);  // byte offset
            const int slB = (((2 * ks + khB) ^ r7) << 4);
            uint4 a0  = ldsm4(aA0 + slA);
            uint4 a1  = ldsm4(aA1 + slA);
            uint4 bb0 = ldsm4(aB0 + slB);   // ni 0,1
            uint4 bb1 = ldsm4(aB1 + slB);   // ni 2,3
            mma_tf32(acc[0][0], a0, bb0.x, bb0.y);
            mma_tf32(acc[0][1], a0, bb0.z, bb0.w);
            mma_tf32(acc[0][2], a0, bb1.x, bb1.y);
            mma_tf32(acc[0][3], a0, bb1.z, bb1.w);
            mma_tf32(acc[1][0], a1, bb0.x, bb0.y);
            mma_tf32(acc[1][1], a1, bb0.z, bb0.w);
            mma_tf32(acc[1][2], a1, bb1.x, bb1.y);
            mma_tf32(acc[1][3], a1, bb1.z, bb1.w);
        }
        __syncthreads();
    }

    // write back + bias
#pragma unroll
    for (int mi = 0; mi < 2; mi++) {
#pragma unroll
        for (int ni = 0; ni < 4; ni++) {
            int r = m0 + wm + mi * 16 + qr;
            int c = n0 + wn + ni * 8 + qc * 2;
            float b0 = bias[c], b1 = bias[c + 1];
            float2 o0 = make_float2(acc[mi][ni][0] + b0, acc[mi][ni][1] + b1);
            float2 o1 = make_float2(acc[mi][ni][2] + b0, acc[mi][ni][3] + b1);
            *reinterpret_cast<float2*>(&Out[(size_t)r * N + c])       = o0;
            *reinterpret_cast<float2*>(&Out[(size_t)(r + 8) * N + c]) = o1;
        }
    }
}

__global__ void __launch_bounds__(256) qkv_gemm_kernel(
    const float* __restrict__ x, const float* __restrict__ qkv_w,
    const float* __restrict__ qkv_b)
{
    gemm_tf32_128x64(x, qkv_w, qkv_b, g_qkv, CDIM, N3);
}

__global__ void __launch_bounds__(256) out_gemm_kernel(
    const float* __restrict__ out_w, const float* __restrict__ out_b,
    float* __restrict__ out)
{
    gemm_tf32_128x64(g_ctx, out_w, out_b, out, CDIM, CDIM);
}

// ---------------------------------------------------------------------------
// Per-window attention. One CTA per window, loops over 8 heads.
// 4x4 register tiles with float4 on both operands (transposed staging).
// mask + rel_index staged once per window (head-invariant).
// ---------------------------------------------------------------------------
#define RS 52

__global__ void __launch_bounds__(256) win_attn_kernel(
    const float* __restrict__ mask, const float* __restrict__ rpe,
    const int* __restrict__ rel_index)
{
    __shared__ float sqT[HD][RS];       // q^T (scaled)  [d][n]
    __shared__ float skT[HD][RS];       // k^T           [d][m]
    __shared__ float sv[NTOK][HD];      // v             [m][d]
    __shared__ float sp[52][RS];        // logits        [n][m]
    __shared__ float spT[52][RS];       // probs^T       [m][n]
    __shared__ float smask[52][RS];     // window mask (zero-padded)
    __shared__ short srel[52 * RS];     // rel_index (zero-padded)

    const int w    = blockIdx.x;
    const int tid  = threadIdx.x;
    const int lane = tid & 31;
    const int warp = tid >> 5;
    const float scale = 0.1767766952966369f; // 32^-0.5

    const float* qb = g_qkv + (size_t)w * NTOK * N3;
    const float* mw = mask + (size_t)(w & 63) * NTOK * NTOK;

    // head-invariant staging: mask + rel_index (padded region zeroed)
    for (int idx = tid; idx < 52 * RS; idx += 256) {
        (&smask[0][0])[idx] = 0.f;
        srel[idx] = 0;
    }
    __syncthreads();
    for (int idx = tid; idx < NTOK * NTOK; idx += 256) {
        int n = idx / 49, m = idx - n * 49;
        smask[n][m] = mw[idx];
        srel[n * RS + m] = (short)rel_index[idx];
    }
    __syncthreads();

    for (int h = 0; h < HEADS_N; h++) {
        const float* rpeh = rpe + h;
        // stage q (scaled, transposed), k (transposed), v
        for (int idx = tid; idx < NTOK * HD; idx += 256) {
            int n = idx >> 5, d = idx & 31;
            const float* r = qb + (size_t)n * N3 + h * HD + d;
            sqT[d][n] = r[0] * scale;
            skT[d][n] = r[CDIM];
            sv[n][d]  = r[2 * CDIM];
        }
        __syncthreads();

        // logits: 4x4 tile per thread, 13x13 = 169 items
        if (tid < 169) {
            int n0 = (tid / 13) * 4, m0 = (tid % 13) * 4;
            float acc[4][4];
#pragma unroll
            for (int r = 0; r < 4; r++)
#pragma unroll
                for (int c = 0; c < 4; c++)
                    acc[r][c] = smask[n0 + r][m0 + c]
                              + rpeh[srel[(n0 + r) * RS + m0 + c] * HEADS_N];
#pragma unroll
            for (int d = 0; d < HD; d++) {
                float4 qv = *reinterpret_cast<const float4*>(&sqT[d][n0]);
                float4 kv = *reinterpret_cast<const float4*>(&skT[d][m0]);
                float q[4] = {qv.x, qv.y, qv.z, qv.w};
                float k[4] = {kv.x, kv.y, kv.z, kv.w};
#pragma unroll
                for (int r = 0; r < 4; r++)
#pragma unroll
                    for (int c = 0; c < 4; c++)
                        acc[r][c] = fmaf(q[r], k[c], acc[r][c]);
            }
#pragma unroll
            for (int r = 0; r < 4; r++)
                *reinterpret_cast<float4*>(&sp[n0 + r][m0]) =
                    make_float4(acc[r][0], acc[r][1], acc[r][2], acc[r][3]);
        }
        __syncthreads();

        // softmax per row; write normalized probs transposed
        for (int n = warp; n < NTOK; n += 8) {
            float a0 = sp[n][lane];
            float a1 = (lane + 32 < NTOK) ? sp[n][lane + 32] : -1e30f;
            float mx = fmaxf(a0, a1);
#pragma unroll
            for (int o = 16; o > 0; o >>= 1)
                mx = fmaxf(mx, __shfl_xor_sync(0xffffffffu, mx, o));
            float e0 = __expf(a0 - mx);
            float e1 = (lane + 32 < NTOK) ? __expf(a1 - mx) : 0.f;
            float s = e0 + e1;
#pragma unroll
            for (int o = 16; o > 0; o >>= 1)
                s += __shfl_xor_sync(0xffffffffu, s, o);
            float inv = 1.f / s;
            spT[lane][n] = e0 * inv;
            if (lane + 32 < NTOK) spT[lane + 32][n] = e1 * inv;
        }
        __syncthreads();

        // ctx = probs @ v : 4n x 4d per thread, 13x8 = 104 items
        if (tid < 104) {
            int n0 = (tid >> 3) << 2, d0 = (tid & 7) << 2;
            float acc[4][4];
#pragma unroll
            for (int r = 0; r < 4; r++)
#pragma unroll
                for (int c = 0; c < 4; c++) acc[r][c] = 0.f;
#pragma unroll 7
            for (int m = 0; m < NTOK; m++) {
                float4 pv = *reinterpret_cast<const float4*>(&spT[m][n0]);
                float4 vv = *reinterpret_cast<const float4*>(&sv[m][d0]);
                float p[4] = {pv.x, pv.y, pv.z, pv.w};
                float v[4] = {vv.x, vv.y, vv.z, vv.w};
#pragma unroll
                for (int r = 0; r < 4; r++)
#pragma unroll
                    for (int c = 0; c < 4; c++)
                        acc[r][c] = fmaf(p[r], v[c], acc[r][c]);
            }
#pragma unroll
            for (int r = 0; r < 4; r++) {
                if (n0 + r < NTOK) {
                    float* o = &g_ctx[((size_t)w * NTOK + n0 + r) * CDIM + h * HD + d0];
                    *reinterpret_cast<float4*>(o) =
                        make_float4(acc[r][0], acc[r][1], acc[r][2], acc[r][3]);
                }
            }
        }
        __syncthreads();
    }
}

// ---------------------------------------------------------------------------
extern "C" void kernel_launch(void* const* d_in, const int* in_sizes, int n_in,
                              void* d_out, int out_size)
{
    const float* x     = (const float*)d_in[0];
    const float* mask  = (const float*)d_in[1];
    const float* qkv_w = (const float*)d_in[2];
    const float* qkv_b = (const float*)d_in[3];
    const float* rpe   = (const float*)d_in[4];
    const float* out_w = (const float*)d_in[5];
    const float* out_b = (const float*)d_in[6];
    const int*   rel   = (const int*)d_in[7];
    float* out = (float*)d_out;

    dim3 g1(N3 / 64, MROWS / 128);    // 12 x 1568
    qkv_gemm_kernel<<<g1, 256>>>(x, qkv_w, qkv_b);

    win_attn_kernel<<<NWIN, 256>>>(mask, rpe, rel);

    dim3 g3(CDIM / 64, MROWS / 128);  // 4 x 1568
    out_gemm_kernel<<<g3, 256>>>(out_w, out_b, out);
}

// round 4
// speedup vs baseline: 2.7755x; 1.1960x over previous
#include <cuda_runtime.h>
#include <cuda_bf16.h>
#include <cstdint>

// ---------------------------------------------------------------------------
// ShiftedWindowAttention (Swin window-MSA)
//   tf32 tensor-core GEMMs: 128x128 block, 64x32 warp tile,
//   2-stage cp.async pipeline, ldmatrix + XOR swizzle, register-side tf32 cvt
// ---------------------------------------------------------------------------

#define NWIN    4096
#define NTOK    49
#define CDIM    256
#define HEADS_N 8
#define HD      32
#define MROWS   (NWIN * NTOK)    // 200704
#define N3      (3 * CDIM)       // 768

__device__ float g_qkv[(size_t)MROWS * N3];   // (M, 768) row-major
__device__ float g_ctx[(size_t)MROWS * CDIM]; // (M, 256) row-major

// ---------------------------------------------------------------------------
// helpers
// ---------------------------------------------------------------------------
__device__ __forceinline__ unsigned f2tf(float x) {
    unsigned u;
    asm("cvt.rna.tf32.f32 %0, %1;" : "=r"(u) : "f"(x));
    return u;
}
__device__ __forceinline__ unsigned f2tf_u(unsigned x) {
    return f2tf(__uint_as_float(x));
}

__device__ __forceinline__ uint32_t s2u(const void* p) {
    return (uint32_t)__cvta_generic_to_shared(p);
}

__device__ __forceinline__ uint4 ldsm4(uint32_t a) {
    uint4 r;
    asm volatile("ldmatrix.sync.aligned.m8n8.x4.shared.b16 {%0,%1,%2,%3}, [%4];"
                 : "=r"(r.x), "=r"(r.y), "=r"(r.z), "=r"(r.w) : "r"(a));
    return r;
}

__device__ __forceinline__ void cpa16(uint32_t dst, const void* src) {
    asm volatile("cp.async.cg.shared.global [%0], [%1], 16;"
                 :: "r"(dst), "l"(src));
}
__device__ __forceinline__ void cpa_commit() {
    asm volatile("cp.async.commit_group;");
}
__device__ __forceinline__ void cpa_wait1() {
    asm volatile("cp.async.wait_group 1;");
}

__device__ __forceinline__ void mma_tf32(float* c, const uint4& a,
                                         unsigned b0, unsigned b1) {
    asm volatile(
        "mma.sync.aligned.m16n8k8.row.col.f32.tf32.tf32.f32 "
        "{%0,%1,%2,%3}, {%4,%5,%6,%7}, {%8,%9}, {%0,%1,%2,%3};"
        : "+f"(c[0]), "+f"(c[1]), "+f"(c[2]), "+f"(c[3])
        : "r"(a.x), "r"(a.y), "r"(a.z), "r"(a.w), "r"(b0), "r"(b1));
}

// ---------------------------------------------------------------------------
// tf32 GEMM:  Out[m,n] = sum_k A[m,k] * W[n,k] + bias[n]
// Block 128x128, 8 warps (2m x 4n), warp tile 64x32, K chunk 32,
// 2-stage cp.async double buffer.
// Smem per stage: A 128x32 + W 128x32 fp32 (raw), 16B-slot XOR swizzle.
// ---------------------------------------------------------------------------
__device__ __forceinline__ void gemm_tf32_128x128(
    const float* __restrict__ A, const float* __restrict__ W,
    const float* __restrict__ bias, float* __restrict__ Out,
    int K, int N)
{
    __shared__ __align__(16) unsigned sbuf[2][8192]; // [stage][A:0..4095|W:4096..8191]

    const int tid  = threadIdx.x;
    const int m0   = blockIdx.y * 128;
    const int n0   = blockIdx.x * 128;
    const int warp = tid >> 5, lane = tid & 31;
    const int qr   = lane >> 2, qc = lane & 3;
    const int wm   = (warp >> 2) * 64;   // 0 or 64
    const int wn   = (warp & 3) * 32;    // 0,32,64,96
    const int g    = lane >> 3;
    const int r7   = lane & 7;
    const int khA  = g >> 1;
    const int khB  = g & 1;

    const float* Ab = A + (size_t)m0 * K;
    const float* Wb = W + (size_t)n0 * K;

    // ldmatrix base byte addresses (stage 0)
    const uint32_t sb = s2u(sbuf);
    uint32_t aA[4], aB[2];
#pragma unroll
    for (int t = 0; t < 4; t++)
        aA[t] = sb + (uint32_t)(wm + 16 * t + (g & 1) * 8 + r7) * 128;
#pragma unroll
    for (int t = 0; t < 2; t++)
        aB[t] = sb + 16384 + (uint32_t)(wn + 16 * t + (g >> 1) * 8 + r7) * 128;

    // staging decomposition (per thread: 4 A + 4 W cp.async of 16B)
    const int srow = tid >> 3;          // 0..31 (+32 per i)
    const int sc4  = (tid & 7) << 2;    // 0..28
    const int slot = (sc4 >> 2);        // pre-XOR slot

    float acc[4][4][4];
#pragma unroll
    for (int t = 0; t < 4; t++)
#pragma unroll
        for (int ni = 0; ni < 4; ni++)
#pragma unroll
            for (int j = 0; j < 4; j++) acc[t][ni][j] = 0.f;

    const int nCh = K >> 5;

    // ---- stage chunks 0 and 1 ----
#pragma unroll
    for (int c = 0; c < 2; c++) {
#pragma unroll
        for (int i = 0; i < 4; i++) {
            int row = srow + i * 32;
            uint32_t d = sb + (uint32_t)c * 32768 +
                         (uint32_t)(row * 32 + ((slot ^ (row & 7)) << 2)) * 4;
            cpa16(d,         Ab + (size_t)row * K + c * 32 + sc4);
            cpa16(d + 16384, Wb + (size_t)row * K + c * 32 + sc4);
        }
        cpa_commit();
    }

    for (int i = 0; i < nCh; i++) {
        cpa_wait1();
        __syncthreads();

        const uint32_t soff = (uint32_t)(i & 1) * 32768;
#pragma unroll
        for (int ks = 0; ks < 4; ks++) {
            const uint32_t offA = (uint32_t)(((2 * ks + khA) ^ r7) << 4) + soff;
            const uint32_t offB = (uint32_t)(((2 * ks + khB) ^ r7) << 4) + soff;
            uint4 af[4], bf[2];
#pragma unroll
            for (int t = 0; t < 4; t++) {
                af[t] = ldsm4(aA[t] + offA);
                af[t].x = f2tf_u(af[t].x); af[t].y = f2tf_u(af[t].y);
                af[t].z = f2tf_u(af[t].z); af[t].w = f2tf_u(af[t].w);
            }
#pragma unroll
            for (int t = 0; t < 2; t++) {
                bf[t] = ldsm4(aB[t] + offB);
                bf[t].x = f2tf_u(bf[t].x); bf[t].y = f2tf_u(bf[t].y);
                bf[t].z = f2tf_u(bf[t].z); bf[t].w = f2tf_u(bf[t].w);
            }
#pragma unroll
            for (int t = 0; t < 4; t++) {
                mma_tf32(acc[t][0], af[t], bf[0].x, bf[0].y);
                mma_tf32(acc[t][1], af[t], bf[0].z, bf[0].w);
                mma_tf32(acc[t][2], af[t], bf[1].x, bf[1].y);
                mma_tf32(acc[t][3], af[t], bf[1].z, bf[1].w);
            }
        }
        __syncthreads();

        if (i + 2 < nCh) {
            const int c = i + 2;
#pragma unroll
            for (int j = 0; j < 4; j++) {
                int row = srow + j * 32;
                uint32_t d = sb + (uint32_t)(i & 1) * 32768 +
                             (uint32_t)(row * 32 + ((slot ^ (row & 7)) << 2)) * 4;
                cpa16(d,         Ab + (size_t)row * K + c * 32 + sc4);
                cpa16(d + 16384, Wb + (size_t)row * K + c * 32 + sc4);
            }
        }
        cpa_commit();   // uniform group accounting (empty group in tail)
    }

    // write back + bias
#pragma unroll
    for (int t = 0; t < 4; t++) {
#pragma unroll
        for (int ni = 0; ni < 4; ni++) {
            int r = m0 + wm + t * 16 + qr;
            int c = n0 + wn + ni * 8 + qc * 2;
            float b0 = bias[c], b1 = bias[c + 1];
            float2 o0 = make_float2(acc[t][ni][0] + b0, acc[t][ni][1] + b1);
            float2 o1 = make_float2(acc[t][ni][2] + b0, acc[t][ni][3] + b1);
            *reinterpret_cast<float2*>(&Out[(size_t)r * N + c])       = o0;
            *reinterpret_cast<float2*>(&Out[(size_t)(r + 8) * N + c]) = o1;
        }
    }
}

__global__ void __launch_bounds__(256, 2) qkv_gemm_kernel(
    const float* __restrict__ x, const float* __restrict__ qkv_w,
    const float* __restrict__ qkv_b)
{
    gemm_tf32_128x128(x, qkv_w, qkv_b, g_qkv, CDIM, N3);
}

__global__ void __launch_bounds__(256, 2) out_gemm_kernel(
    const float* __restrict__ out_w, const float* __restrict__ out_b,
    float* __restrict__ out)
{
    gemm_tf32_128x128(g_ctx, out_w, out_b, out, CDIM, CDIM);
}

// ---------------------------------------------------------------------------
// Per-window attention (unchanged from R3 — passing, ~860us; mma rewrite is
// the planned R5 step).
// ---------------------------------------------------------------------------
#define RS 52

__global__ void __launch_bounds__(256) win_attn_kernel(
    const float* __restrict__ mask, const float* __restrict__ rpe,
    const int* __restrict__ rel_index)
{
    __shared__ float sqT[HD][RS];
    __shared__ float skT[HD][RS];
    __shared__ float sv[NTOK][HD];
    __shared__ float sp[52][RS];
    __shared__ float spT[52][RS];
    __shared__ float smask[52][RS];
    __shared__ short srel[52 * RS];

    const int w    = blockIdx.x;
    const int tid  = threadIdx.x;
    const int lane = tid & 31;
    const int warp = tid >> 5;
    const float scale = 0.1767766952966369f;

    const float* qb = g_qkv + (size_t)w * NTOK * N3;
    const float* mw = mask + (size_t)(w & 63) * NTOK * NTOK;

    for (int idx = tid; idx < 52 * RS; idx += 256) {
        (&smask[0][0])[idx] = 0.f;
        srel[idx] = 0;
    }
    __syncthreads();
    for (int idx = tid; idx < NTOK * NTOK; idx += 256) {
        int n = idx / 49, m = idx - n * 49;
        smask[n][m] = mw[idx];
        srel[n * RS + m] = (short)rel_index[idx];
    }
    __syncthreads();

    for (int h = 0; h < HEADS_N; h++) {
        const float* rpeh = rpe + h;
        for (int idx = tid; idx < NTOK * HD; idx += 256) {
            int n = idx >> 5, d = idx & 31;
            const float* r = qb + (size_t)n * N3 + h * HD + d;
            sqT[d][n] = r[0] * scale;
            skT[d][n] = r[CDIM];
            sv[n][d]  = r[2 * CDIM];
        }
        __syncthreads();

        if (tid < 169) {
            int n0 = (tid / 13) * 4, m0 = (tid % 13) * 4;
            float acc[4][4];
#pragma unroll
            for (int r = 0; r < 4; r++)
#pragma unroll
                for (int c = 0; c < 4; c++)
                    acc[r][c] = smask[n0 + r][m0 + c]
                              + rpeh[srel[(n0 + r) * RS + m0 + c] * HEADS_N];
#pragma unroll
            for (int d = 0; d < HD; d++) {
                float4 qv = *reinterpret_cast<const float4*>(&sqT[d][n0]);
                float4 kv = *reinterpret_cast<const float4*>(&skT[d][m0]);
                float q[4] = {qv.x, qv.y, qv.z, qv.w};
                float k[4] = {kv.x, kv.y, kv.z, kv.w};
#pragma unroll
                for (int r = 0; r < 4; r++)
#pragma unroll
                    for (int c = 0; c < 4; c++)
                        acc[r][c] = fmaf(q[r], k[c], acc[r][c]);
            }
#pragma unroll
            for (int r = 0; r < 4; r++)
                *reinterpret_cast<float4*>(&sp[n0 + r][m0]) =
                    make_float4(acc[r][0], acc[r][1], acc[r][2], acc[r][3]);
        }
        __syncthreads();

        for (int n = warp; n < NTOK; n += 8) {
            float a0 = sp[n][lane];
            float a1 = (lane + 32 < NTOK) ? sp[n][lane + 32] : -1e30f;
            float mx = fmaxf(a0, a1);
#pragma unroll
            for (int o = 16; o > 0; o >>= 1)
                mx = fmaxf(mx, __shfl_xor_sync(0xffffffffu, mx, o));
            float e0 = __expf(a0 - mx);
            float e1 = (lane + 32 < NTOK) ? __expf(a1 - mx) : 0.f;
            float s = e0 + e1;
#pragma unroll
            for (int o = 16; o > 0; o >>= 1)
                s += __shfl_xor_sync(0xffffffffu, s, o);
            float inv = 1.f / s;
            spT[lane][n] = e0 * inv;
            if (lane + 32 < NTOK) spT[lane + 32][n] = e1 * inv;
        }
        __syncthreads();

        if (tid < 104) {
            int n0 = (tid >> 3) << 2, d0 = (tid & 7) << 2;
            float acc[4][4];
#pragma unroll
            for (int r = 0; r < 4; r++)
#pragma unroll
                for (int c = 0; c < 4; c++) acc[r][c] = 0.f;
#pragma unroll 7
            for (int m = 0; m < NTOK; m++) {
                float4 pv = *reinterpret_cast<const float4*>(&spT[m][n0]);
                float4 vv = *reinterpret_cast<const float4*>(&sv[m][d0]);
                float p[4] = {pv.x, pv.y, pv.z, pv.w};
                float v[4] = {vv.x, vv.y, vv.z, vv.w};
#pragma unroll
                for (int r = 0; r < 4; r++)
#pragma unroll
                    for (int c = 0; c < 4; c++)
                        acc[r][c] = fmaf(p[r], v[c], acc[r][c]);
            }
#pragma unroll
            for (int r = 0; r < 4; r++) {
                if (n0 + r < NTOK) {
                    float* o = &g_ctx[((size_t)w * NTOK + n0 + r) * CDIM + h * HD + d0];
                    *reinterpret_cast<float4*>(o) =
                        make_float4(acc[r][0], acc[r][1], acc[r][2], acc[r][3]);
                }
            }
        }
        __syncthreads();
    }
}

// ---------------------------------------------------------------------------
extern "C" void kernel_launch(void* const* d_in, const int* in_sizes, int n_in,
                              void* d_out, int out_size)
{
    const float* x     = (const float*)d_in[0];
    const float* mask  = (const float*)d_in[1];
    const float* qkv_w = (const float*)d_in[2];
    const float* qkv_b = (const float*)d_in[3];
    const float* rpe   = (const float*)d_in[4];
    const float* out_w = (const float*)d_in[5];
    const float* out_b = (const float*)d_in[6];
    const int*   rel   = (const int*)d_in[7];
    float* out = (float*)d_out;

    dim3 g1(N3 / 128, MROWS / 128);   // 6 x 1568
    qkv_gemm_kernel<<<g1, 256>>>(x, qkv_w, qkv_b);

    win_attn_kernel<<<NWIN, 256>>>(mask, rpe, rel);

    dim3 g3(CDIM / 128, MROWS / 128); // 2 x 1568
    out_gemm_kernel<<<g3, 256>>>(out_w, out_b, out);
}

// round 5
// speedup vs baseline: 3.9031x; 1.4063x over previous
#include <cuda_runtime.h>
#include <cuda_bf16.h>
#include <cstdint>

// ---------------------------------------------------------------------------
// ShiftedWindowAttention (Swin window-MSA)
//   Stage 1/3: tf32 GEMMs (128x128, cp.async double buffer)  [unchanged R4]
//   Stage 2:   tensor-core window attention, warp = (window, head)
// ---------------------------------------------------------------------------

#define NWIN    4096
#define NTOK    49
#define CDIM    256
#define HEADS_N 8
#define HD      32
#define MROWS   (NWIN * NTOK)    // 200704
#define N3      (3 * CDIM)       // 768

__device__ float g_qkv[(size_t)MROWS * N3];   // (M, 768) row-major
__device__ float g_ctx[(size_t)MROWS * CDIM]; // (M, 256) row-major

// ---------------------------------------------------------------------------
// helpers
// ---------------------------------------------------------------------------
__device__ __forceinline__ unsigned f2tf(float x) {
    unsigned u;
    asm("cvt.rna.tf32.f32 %0, %1;" : "=r"(u) : "f"(x));
    return u;
}
__device__ __forceinline__ unsigned f2tf_u(unsigned x) {
    return f2tf(__uint_as_float(x));
}

__device__ __forceinline__ uint32_t s2u(const void* p) {
    return (uint32_t)__cvta_generic_to_shared(p);
}

__device__ __forceinline__ uint4 ldsm4(uint32_t a) {
    uint4 r;
    asm volatile("ldmatrix.sync.aligned.m8n8.x4.shared.b16 {%0,%1,%2,%3}, [%4];"
                 : "=r"(r.x), "=r"(r.y), "=r"(r.z), "=r"(r.w) : "r"(a));
    return r;
}

__device__ __forceinline__ void cpa16(uint32_t dst, const void* src) {
    asm volatile("cp.async.cg.shared.global [%0], [%1], 16;"
                 :: "r"(dst), "l"(src));
}
__device__ __forceinline__ void cpa_commit() {
    asm volatile("cp.async.commit_group;");
}
__device__ __forceinline__ void cpa_wait1() {
    asm volatile("cp.async.wait_group 1;");
}

__device__ __forceinline__ void mma_tf32(float* c, const uint4& a,
                                         unsigned b0, unsigned b1) {
    asm volatile(
        "mma.sync.aligned.m16n8k8.row.col.f32.tf32.tf32.f32 "
        "{%0,%1,%2,%3}, {%4,%5,%6,%7}, {%8,%9}, {%0,%1,%2,%3};"
        : "+f"(c[0]), "+f"(c[1]), "+f"(c[2]), "+f"(c[3])
        : "r"(a.x), "r"(a.y), "r"(a.z), "r"(a.w), "r"(b0), "r"(b1));
}

// ---------------------------------------------------------------------------
// tf32 GEMM (unchanged from R4)
// ---------------------------------------------------------------------------
__device__ __forceinline__ void gemm_tf32_128x128(
    const float* __restrict__ A, const float* __restrict__ W,
    const float* __restrict__ bias, float* __restrict__ Out,
    int K, int N)
{
    __shared__ __align__(16) unsigned sbuf[2][8192];

    const int tid  = threadIdx.x;
    const int m0   = blockIdx.y * 128;
    const int n0   = blockIdx.x * 128;
    const int warp = tid >> 5, lane = tid & 31;
    const int qr   = lane >> 2, qc = lane & 3;
    const int wm   = (warp >> 2) * 64;
    const int wn   = (warp & 3) * 32;
    const int g    = lane >> 3;
    const int r7   = lane & 7;
    const int khA  = g >> 1;
    const int khB  = g & 1;

    const float* Ab = A + (size_t)m0 * K;
    const float* Wb = W + (size_t)n0 * K;

    const uint32_t sb = s2u(sbuf);
    uint32_t aA[4], aB[2];
#pragma unroll
    for (int t = 0; t < 4; t++)
        aA[t] = sb + (uint32_t)(wm + 16 * t + (g & 1) * 8 + r7) * 128;
#pragma unroll
    for (int t = 0; t < 2; t++)
        aB[t] = sb + 16384 + (uint32_t)(wn + 16 * t + (g >> 1) * 8 + r7) * 128;

    const int srow = tid >> 3;
    const int sc4  = (tid & 7) << 2;
    const int slot = (sc4 >> 2);

    float acc[4][4][4];
#pragma unroll
    for (int t = 0; t < 4; t++)
#pragma unroll
        for (int ni = 0; ni < 4; ni++)
#pragma unroll
            for (int j = 0; j < 4; j++) acc[t][ni][j] = 0.f;

    const int nCh = K >> 5;

#pragma unroll
    for (int c = 0; c < 2; c++) {
#pragma unroll
        for (int i = 0; i < 4; i++) {
            int row = srow + i * 32;
            uint32_t d = sb + (uint32_t)c * 32768 +
                         (uint32_t)(row * 32 + ((slot ^ (row & 7)) << 2)) * 4;
            cpa16(d,         Ab + (size_t)row * K + c * 32 + sc4);
            cpa16(d + 16384, Wb + (size_t)row * K + c * 32 + sc4);
        }
        cpa_commit();
    }

    for (int i = 0; i < nCh; i++) {
        cpa_wait1();
        __syncthreads();

        const uint32_t soff = (uint32_t)(i & 1) * 32768;
#pragma unroll
        for (int ks = 0; ks < 4; ks++) {
            const uint32_t offA = (uint32_t)(((2 * ks + khA) ^ r7) << 4) + soff;
            const uint32_t offB = (uint32_t)(((2 * ks + khB) ^ r7) << 4) + soff;
            uint4 af[4], bf[2];
#pragma unroll
            for (int t = 0; t < 4; t++) {
                af[t] = ldsm4(aA[t] + offA);
                af[t].x = f2tf_u(af[t].x); af[t].y = f2tf_u(af[t].y);
                af[t].z = f2tf_u(af[t].z); af[t].w = f2tf_u(af[t].w);
            }
#pragma unroll
            for (int t = 0; t < 2; t++) {
                bf[t] = ldsm4(aB[t] + offB);
                bf[t].x = f2tf_u(bf[t].x); bf[t].y = f2tf_u(bf[t].y);
                bf[t].z = f2tf_u(bf[t].z); bf[t].w = f2tf_u(bf[t].w);
            }
#pragma unroll
            for (int t = 0; t < 4; t++) {
                mma_tf32(acc[t][0], af[t], bf[0].x, bf[0].y);
                mma_tf32(acc[t][1], af[t], bf[0].z, bf[0].w);
                mma_tf32(acc[t][2], af[t], bf[1].x, bf[1].y);
                mma_tf32(acc[t][3], af[t], bf[1].z, bf[1].w);
            }
        }
        __syncthreads();

        if (i + 2 < nCh) {
            const int c = i + 2;
#pragma unroll
            for (int j = 0; j < 4; j++) {
                int row = srow + j * 32;
                uint32_t d = sb + (uint32_t)(i & 1) * 32768 +
                             (uint32_t)(row * 32 + ((slot ^ (row & 7)) << 2)) * 4;
                cpa16(d,         Ab + (size_t)row * K + c * 32 + sc4);
                cpa16(d + 16384, Wb + (size_t)row * K + c * 32 + sc4);
            }
        }
        cpa_commit();
    }

#pragma unroll
    for (int t = 0; t < 4; t++) {
#pragma unroll
        for (int ni = 0; ni < 4; ni++) {
            int r = m0 + wm + t * 16 + qr;
            int c = n0 + wn + ni * 8 + qc * 2;
            float b0 = bias[c], b1 = bias[c + 1];
            float2 o0 = make_float2(acc[t][ni][0] + b0, acc[t][ni][1] + b1);
            float2 o1 = make_float2(acc[t][ni][2] + b0, acc[t][ni][3] + b1);
            *reinterpret_cast<float2*>(&Out[(size_t)r * N + c])       = o0;
            *reinterpret_cast<float2*>(&Out[(size_t)(r + 8) * N + c]) = o1;
        }
    }
}

__global__ void __launch_bounds__(256, 2) qkv_gemm_kernel(
    const float* __restrict__ x, const float* __restrict__ qkv_w,
    const float* __restrict__ qkv_b)
{
    gemm_tf32_128x128(x, qkv_w, qkv_b, g_qkv, CDIM, N3);
}

__global__ void __launch_bounds__(256, 2) out_gemm_kernel(
    const float* __restrict__ out_w, const float* __restrict__ out_b,
    float* __restrict__ out)
{
    gemm_tf32_128x128(g_ctx, out_w, out_b, out, CDIM, CDIM);
}

// ---------------------------------------------------------------------------
// Tensor-core window attention.
// CTA = 128 threads = 4 warps = 1 window; warp j handles heads j and j+4.
// Per head, per warp-private smem slice (tf32 bits, 32/64-word rows with
// 16B-slot XOR swizzle, same fragment scheme as the GEMM):
//   Q [64][32]  (rows 49..63 garbage -> outputs never stored)
//   K [64][32]  (rows 49..63 garbage -> logit cols >=49 forced to -1e30)
//   VT[32][64]  (cols 49..63 zeroed  -> P there is exactly 0)
// S = Q K^T (128 mma) -> +mask+rpe bias -> quad-shuffle softmax ->
// register permute of P into A-fragment layout -> C = P V (128 mma).
// ---------------------------------------------------------------------------
#define WBUF_WORDS 6144          // per-warp: Q 2048 | K 2048 | VT 2048
#define SM_MASK_OFF (4 * WBUF_WORDS * 4)           // 98304
#define SM_REL_OFF  (SM_MASK_OFF + 64 * 56 * 2)    // 105472
#define SMEM_ATTN   (SM_REL_OFF + 64 * 56)         // 109056

__global__ void __launch_bounds__(128) win_attn_kernel(
    const float* __restrict__ mask, const float* __restrict__ rpe,
    const int* __restrict__ rel_index)
{
    extern __shared__ __align__(16) char smem[];

    const int w    = blockIdx.x;
    const int tid  = threadIdx.x;
    const int lane = tid & 31;
    const int warp = tid >> 5;
    const int qr   = lane >> 2, qc = lane & 3;
    const int g    = lane >> 3, r7 = lane & 7;
    const float scale = 0.1767766952966369f; // 32^-0.5

    unsigned* wbuf = reinterpret_cast<unsigned*>(smem) + warp * WBUF_WORDS;
    unsigned* Qw  = wbuf;
    unsigned* Kw  = wbuf + 2048;
    unsigned* VTw = wbuf + 4096;
    __nv_bfloat16* smask = reinterpret_cast<__nv_bfloat16*>(smem + SM_MASK_OFF);
    uint8_t*       srel  = reinterpret_cast<uint8_t*>(smem + SM_REL_OFF);

    const uint32_t qb = s2u(Qw), kb = s2u(Kw), vb = s2u(VTw);

    // ---- head-invariant staging: mask (bf16) + rel index (u8), padded ----
    const float* mw = mask + (size_t)(w & 63) * NTOK * NTOK;
    for (int idx = tid; idx < 64 * 56; idx += 128) {
        int n = idx / 56, m = idx - n * 56;
        bool v = (n < NTOK) && (m < NTOK);
        smask[idx] = __float2bfloat16(v ? mw[n * NTOK + m] : 0.f);
        srel[idx]  = v ? (uint8_t)rel_index[n * NTOK + m] : (uint8_t)0;
    }
    __syncthreads();

    const float* base0 = g_qkv + (size_t)w * NTOK * N3;

#pragma unroll 1
    for (int hi = 0; hi < 2; hi++) {
        const int h = warp + hi * 4;
        const float* qbase = base0 + h * HD;

        __syncwarp();
        // zero VT (padding cols must be exactly 0)
        for (int i = lane; i < 512; i += 32)
            *reinterpret_cast<uint4*>(&VTw[i * 4]) = make_uint4(0, 0, 0, 0);

        // stage Q (scaled) and K, tf32 bits, swizzled rows of 32 words
        for (int it = lane; it < NTOK * 8; it += 32) {
            int n = it >> 3, c4 = (it & 7) << 2;
            const float* r = qbase + (size_t)n * N3 + c4;
            float4 vq = *reinterpret_cast<const float4*>(r);
            float4 vk = *reinterpret_cast<const float4*>(r + CDIM);
            int off = n * 32 + ((c4 >> 2) ^ (n & 7)) * 4;
            *reinterpret_cast<uint4*>(&Qw[off]) =
                make_uint4(f2tf(vq.x * scale), f2tf(vq.y * scale),
                           f2tf(vq.z * scale), f2tf(vq.w * scale));
            *reinterpret_cast<uint4*>(&Kw[off]) =
                make_uint4(f2tf(vk.x), f2tf(vk.y), f2tf(vk.z), f2tf(vk.w));
        }
        // stage V transposed: VT[d][m], rows of 64 words, swizzled
        for (int it = lane; it < NTOK * 8; it += 32) {
            int m = it >> 3, d4 = (it & 7) << 2;
            float4 vv = *reinterpret_cast<const float4*>(
                qbase + (size_t)m * N3 + 2 * CDIM + d4);
            float e[4] = {vv.x, vv.y, vv.z, vv.w};
#pragma unroll
            for (int ee = 0; ee < 4; ee++) {
                int d = d4 + ee;
                VTw[d * 64 + (((m >> 2) ^ (d & 7)) << 2) + (m & 3)] = f2tf(e[ee]);
            }
        }
        __syncwarp();

#pragma unroll 1
        for (int half = 0; half < 2; half++) {
            // ---- S = Q K^T ----
            float acc[2][8][4];
#pragma unroll
            for (int mt = 0; mt < 2; mt++)
#pragma unroll
                for (int nt = 0; nt < 8; nt++)
#pragma unroll
                    for (int j = 0; j < 4; j++) acc[mt][nt][j] = 0.f;

#pragma unroll
            for (int ks = 0; ks < 4; ks++) {
                uint4 af[2];
#pragma unroll
                for (int mt = 0; mt < 2; mt++) {
                    int row = half * 32 + mt * 16 + (g & 1) * 8 + r7;
                    af[mt] = ldsm4(qb + row * 128 +
                                   (((2 * ks + (g >> 1)) ^ r7) << 4));
                }
#pragma unroll
                for (int p = 0; p < 4; p++) {
                    int rowb = p * 16 + (g >> 1) * 8 + r7;
                    uint4 bb = ldsm4(kb + rowb * 128 +
                                     (((2 * ks + (g & 1)) ^ r7) << 4));
#pragma unroll
                    for (int mt = 0; mt < 2; mt++) {
                        mma_tf32(acc[mt][2 * p],     af[mt], bb.x, bb.y);
                        mma_tf32(acc[mt][2 * p + 1], af[mt], bb.z, bb.w);
                    }
                }
            }

            // ---- bias + mask (cols >=49 -> -1e30) ----
#pragma unroll
            for (int mt = 0; mt < 2; mt++) {
                int r0 = half * 32 + mt * 16 + qr;
                int r1 = r0 + 8;
#pragma unroll
                for (int nt = 0; nt < 8; nt++) {
                    int m0 = nt * 8 + 2 * qc;
                    if (m0 < NTOK) {
                        float b0a = __bfloat162float(smask[r0 * 56 + m0])
                                  + rpe[(int)srel[r0 * 56 + m0] * HEADS_N + h];
                        float b0b = __bfloat162float(smask[r1 * 56 + m0])
                                  + rpe[(int)srel[r1 * 56 + m0] * HEADS_N + h];
                        acc[mt][nt][0] += b0a;
                        acc[mt][nt][2] += b0b;
                    } else {
                        acc[mt][nt][0] = -1e30f;
                        acc[mt][nt][2] = -1e30f;
                    }
                    int m1 = m0 + 1;
                    if (m1 < NTOK) {
                        float b1a = __bfloat162float(smask[r0 * 56 + m1])
                                  + rpe[(int)srel[r0 * 56 + m1] * HEADS_N + h];
                        float b1b = __bfloat162float(smask[r1 * 56 + m1])
                                  + rpe[(int)srel[r1 * 56 + m1] * HEADS_N + h];
                        acc[mt][nt][1] += b1a;
                        acc[mt][nt][3] += b1b;
                    } else {
                        acc[mt][nt][1] = -1e30f;
                        acc[mt][nt][3] = -1e30f;
                    }
                }
            }

            // ---- softmax per row (row spread across quad lanes) ----
#pragma unroll
            for (int mt = 0; mt < 2; mt++) {
                float mx0 = -1e30f, mx1 = -1e30f;
#pragma unroll
                for (int nt = 0; nt < 8; nt++) {
                    mx0 = fmaxf(mx0, fmaxf(acc[mt][nt][0], acc[mt][nt][1]));
                    mx1 = fmaxf(mx1, fmaxf(acc[mt][nt][2], acc[mt][nt][3]));
                }
#pragma unroll
                for (int o = 1; o < 4; o <<= 1) {
                    mx0 = fmaxf(mx0, __shfl_xor_sync(0xffffffffu, mx0, o));
                    mx1 = fmaxf(mx1, __shfl_xor_sync(0xffffffffu, mx1, o));
                }
                float s0 = 0.f, s1 = 0.f;
#pragma unroll
                for (int nt = 0; nt < 8; nt++) {
                    acc[mt][nt][0] = __expf(acc[mt][nt][0] - mx0);
                    acc[mt][nt][1] = __expf(acc[mt][nt][1] - mx0);
                    acc[mt][nt][2] = __expf(acc[mt][nt][2] - mx1);
                    acc[mt][nt][3] = __expf(acc[mt][nt][3] - mx1);
                    s0 += acc[mt][nt][0] + acc[mt][nt][1];
                    s1 += acc[mt][nt][2] + acc[mt][nt][3];
                }
#pragma unroll
                for (int o = 1; o < 4; o <<= 1) {
                    s0 += __shfl_xor_sync(0xffffffffu, s0, o);
                    s1 += __shfl_xor_sync(0xffffffffu, s1, o);
                }
                float i0 = 1.f / s0, i1 = 1.f / s1;
#pragma unroll
                for (int nt = 0; nt < 8; nt++) {
                    acc[mt][nt][0] *= i0; acc[mt][nt][1] *= i0;
                    acc[mt][nt][2] *= i1; acc[mt][nt][3] *= i1;
                }
            }

            // ---- C = P V : permute P into A-fragment layout, mma with VT ----
            float cacc[2][4][4];
#pragma unroll
            for (int mt = 0; mt < 2; mt++)
#pragma unroll
                for (int dt = 0; dt < 4; dt++)
#pragma unroll
                    for (int j = 0; j < 4; j++) cacc[mt][dt][j] = 0.f;

            const int sbase = lane & ~3;
            const int sL = sbase + (qc >> 1);
            const int sH = sL + 2;
            const bool podd = qc & 1;

#pragma unroll
            for (int j = 0; j < 8; j++) {
                uint4 aP[2];
#pragma unroll
                for (int mt = 0; mt < 2; mt++) {
                    float c0 = acc[mt][j][0], c1 = acc[mt][j][1];
                    float c2 = acc[mt][j][2], c3 = acc[mt][j][3];
                    float t0 = __shfl_sync(0xffffffffu, c0, sL);
                    float t1 = __shfl_sync(0xffffffffu, c1, sL);
                    float u0 = __shfl_sync(0xffffffffu, c0, sH);
                    float u1 = __shfl_sync(0xffffffffu, c1, sH);
                    float v0 = __shfl_sync(0xffffffffu, c2, sL);
                    float v1 = __shfl_sync(0xffffffffu, c3, sL);
                    float w0 = __shfl_sync(0xffffffffu, c2, sH);
                    float w1 = __shfl_sync(0xffffffffu, c3, sH);
                    aP[mt].x = f2tf(podd ? t1 : t0);   // (qr,   8j+qc)
                    aP[mt].y = f2tf(podd ? v1 : v0);   // (qr+8, 8j+qc)
                    aP[mt].z = f2tf(podd ? u1 : u0);   // (qr,   8j+qc+4)
                    aP[mt].w = f2tf(podd ? w1 : w0);   // (qr+8, 8j+qc+4)
                }
                uint32_t voff = (((2 * j + (g & 1)) ^ r7) << 4);
                uint4 b0 = ldsm4(vb + ((g >> 1) * 8 + r7) * 256 + voff);
                uint4 b1 = ldsm4(vb + (16 + (g >> 1) * 8 + r7) * 256 + voff);
#pragma unroll
                for (int mt = 0; mt < 2; mt++) {
                    mma_tf32(cacc[mt][0], aP[mt], b0.x, b0.y);
                    mma_tf32(cacc[mt][1], aP[mt], b0.z, b0.w);
                    mma_tf32(cacc[mt][2], aP[mt], b1.x, b1.y);
                    mma_tf32(cacc[mt][3], aP[mt], b1.z, b1.w);
                }
            }

            // ---- store ctx ----
#pragma unroll
            for (int mt = 0; mt < 2; mt++) {
                int n0 = half * 32 + mt * 16 + qr;
#pragma unroll
                for (int dt = 0; dt < 4; dt++) {
                    int col = h * HD + dt * 8 + 2 * qc;
                    if (n0 < NTOK)
                        *reinterpret_cast<float2*>(
                            &g_ctx[((size_t)w * NTOK + n0) * CDIM + col]) =
                            make_float2(cacc[mt][dt][0], cacc[mt][dt][1]);
                    if (n0 + 8 < NTOK)
                        *reinterpret_cast<float2*>(
                            &g_ctx[((size_t)w * NTOK + n0 + 8) * CDIM + col]) =
                            make_float2(cacc[mt][dt][2], cacc[mt][dt][3]);
                }
            }
        }
    }
}

// ---------------------------------------------------------------------------
extern "C" void kernel_launch(void* const* d_in, const int* in_sizes, int n_in,
                              void* d_out, int out_size)
{
    const float* x     = (const float*)d_in[0];
    const float* mask  = (const float*)d_in[1];
    const float* qkv_w = (const float*)d_in[2];
    const float* qkv_b = (const float*)d_in[3];
    const float* rpe   = (const float*)d_in[4];
    const float* out_w = (const float*)d_in[5];
    const float* out_b = (const float*)d_in[6];
    const int*   rel   = (const int*)d_in[7];
    float* out = (float*)d_out;

    cudaFuncSetAttribute(win_attn_kernel,
                         cudaFuncAttributeMaxDynamicSharedMemorySize, SMEM_ATTN);

    dim3 g1(N3 / 128, MROWS / 128);   // 6 x 1568
    qkv_gemm_kernel<<<g1, 256>>>(x, qkv_w, qkv_b);

    win_attn_kernel<<<NWIN, 128, SMEM_ATTN>>>(mask, rpe, rel);

    dim3 g3(CDIM / 128, MROWS / 128); // 2 x 1568
    out_gemm_kernel<<<g3, 256>>>(out_w, out_b, out);
}

// round 7
// speedup vs baseline: 4.5015x; 1.1533x over previous
#include <cuda_runtime.h>
#include <cuda_fp16.h>
#include <cuda_bf16.h>
#include <cstdint>

// ---------------------------------------------------------------------------
// ShiftedWindowAttention (Swin window-MSA)
//   Stage 0: prepass converts x / weights to fp16 (gmem)
//   Stage 1/3: fp16 mma.m16n8k16 GEMMs, fp32 accum, cp.async double buffer
//   Stage 2:   tf32 tensor-core window attention (R5), epilogue writes fp16 ctx
// ---------------------------------------------------------------------------

#define NWIN    4096
#define NTOK    49
#define CDIM    256
#define HEADS_N 8
#define HD      32
#define MROWS   (NWIN * NTOK)    // 200704
#define N3      (3 * CDIM)       // 768

__device__ float  g_qkv[(size_t)MROWS * N3];    // (M, 768) fp32
__device__ __half g_xh[(size_t)MROWS * CDIM];   // x as fp16
__device__ __half g_ctxh[(size_t)MROWS * CDIM]; // ctx as fp16
__device__ __half g_wqkvh[N3 * CDIM];           // qkv_w as fp16
__device__ __half g_wouth[CDIM * CDIM];         // out_w as fp16

// ---------------------------------------------------------------------------
// helpers
// ---------------------------------------------------------------------------
__device__ __forceinline__ unsigned f2tf(float x) {
    unsigned u;
    asm("cvt.rna.tf32.f32 %0, %1;" : "=r"(u) : "f"(x));
    return u;
}

__device__ __forceinline__ uint32_t f2h2(float lo, float hi) {
    uint32_t u;
    asm("cvt.rn.f16x2.f32 %0, %1, %2;" : "=r"(u) : "f"(hi), "f"(lo));
    return u;
}

__device__ __forceinline__ uint32_t s2u(const void* p) {
    return (uint32_t)__cvta_generic_to_shared(p);
}

__device__ __forceinline__ uint4 ldsm4(uint32_t a) {
    uint4 r;
    asm volatile("ldmatrix.sync.aligned.m8n8.x4.shared.b16 {%0,%1,%2,%3}, [%4];"
                 : "=r"(r.x), "=r"(r.y), "=r"(r.z), "=r"(r.w) : "r"(a));
    return r;
}

__device__ __forceinline__ void cpa16(uint32_t dst, const void* src) {
    asm volatile("cp.async.cg.shared.global [%0], [%1], 16;"
                 :: "r"(dst), "l"(src));
}
__device__ __forceinline__ void cpa_commit() {
    asm volatile("cp.async.commit_group;");
}
__device__ __forceinline__ void cpa_wait1() {
    asm volatile("cp.async.wait_group 1;");
}

// fp16 mma: D(4xf32) = A(16x16 f16, 4 regs) * B(16x8 f16, 2 regs) + D
__device__ __forceinline__ void mma_f16(float* c, const uint4& a,
                                        unsigned b0, unsigned b1) {
    asm volatile(
        "mma.sync.aligned.m16n8k16.row.col.f32.f16.f16.f32 "
        "{%0,%1,%2,%3}, {%4,%5,%6,%7}, {%8,%9}, {%0,%1,%2,%3};"
        : "+f"(c[0]), "+f"(c[1]), "+f"(c[2]), "+f"(c[3])
        : "r"(a.x), "r"(a.y), "r"(a.z), "r"(a.w), "r"(b0), "r"(b1));
}

// tf32 mma (attention)
__device__ __forceinline__ void mma_tf32(float* c, const uint4& a,
                                         unsigned b0, unsigned b1) {
    asm volatile(
        "mma.sync.aligned.m16n8k8.row.col.f32.tf32.tf32.f32 "
        "{%0,%1,%2,%3}, {%4,%5,%6,%7}, {%8,%9}, {%0,%1,%2,%3};"
        : "+f"(c[0]), "+f"(c[1]), "+f"(c[2]), "+f"(c[3])
        : "r"(a.x), "r"(a.y), "r"(a.z), "r"(a.w), "r"(b0), "r"(b1));
}

// ---------------------------------------------------------------------------
// prepass: fp32 -> fp16 conversions
// ---------------------------------------------------------------------------
__global__ void __launch_bounds__(256) cvt_x_kernel(const float* __restrict__ x)
{
    int i = blockIdx.x * 256 + threadIdx.x;           // float4 index
    float4 v = reinterpret_cast<const float4*>(x)[i];
    reinterpret_cast<uint2*>(g_xh)[i] =
        make_uint2(f2h2(v.x, v.y), f2h2(v.z, v.w));
}

__global__ void __launch_bounds__(256) cvt_w_kernel(
    const float* __restrict__ qkv_w, const float* __restrict__ out_w)
{
    int i = blockIdx.x * 256 + threadIdx.x;           // float4 index
    if (i < (N3 * CDIM) / 4) {
        float4 v = reinterpret_cast<const float4*>(qkv_w)[i];
        reinterpret_cast<uint2*>(g_wqkvh)[i] =
            make_uint2(f2h2(v.x, v.y), f2h2(v.z, v.w));
    } else {
        int j = i - (N3 * CDIM) / 4;
        float4 v = reinterpret_cast<const float4*>(out_w)[j];
        reinterpret_cast<uint2*>(g_wouth)[j] =
            make_uint2(f2h2(v.x, v.y), f2h2(v.z, v.w));
    }
}

// ---------------------------------------------------------------------------
// fp16 GEMM:  Out[m,n] = sum_k A[m,k] * W[n,k] + bias[n]   (K = 256)
// Block 128x128, 8 warps (2m x 4n), warp tile 64x32, K chunk 64 halves,
// 2-stage cp.async double buffer. SMEM rows: 64 halves = 128 B, SW128-style
// 16B-slot XOR swizzle (slot ^= row&7); fragments via ldmatrix (b16 native).
// ---------------------------------------------------------------------------
#define GEMM_SMEM 65536   // 2 stages x (A 16KB + W 16KB)

__device__ __forceinline__ void stage_chunk_h(
    const __half* __restrict__ Ah, const __half* __restrict__ Wh,
    int m0, int n0, int c, uint32_t dstbase, int tid)
{
    const int rr   = tid >> 1;            // 0..127
    const int segb = (tid & 1) * 4;       // 0 or 4
    const char* As = reinterpret_cast<const char*>(Ah) +
                     (size_t)(m0 + rr) * 512 + c * 128;
    const char* Ws = reinterpret_cast<const char*>(Wh) +
                     (size_t)(n0 + rr) * 512 + c * 128;
    const uint32_t drow = dstbase + rr * 128;
#pragma unroll
    for (int i = 0; i < 4; i++) {
        int seg = segb + i;
        uint32_t d = drow + ((seg ^ (rr & 7)) << 4);
        cpa16(d,         As + seg * 16);
        cpa16(d + 16384, Ws + seg * 16);
    }
}

__device__ __forceinline__ void gemm_f16_body(
    const __half* __restrict__ Ah, const __half* __restrict__ Wh,
    const float* __restrict__ bias, float* __restrict__ Out, int N)
{
    __shared__ __align__(16) char sbuf[GEMM_SMEM];

    const int tid  = threadIdx.x;
    const int m0   = blockIdx.y * 128;
    const int n0   = blockIdx.x * 128;
    const int warp = tid >> 5, lane = tid & 31;
    const int qr   = lane >> 2, qc = lane & 3;
    const int wm   = (warp >> 2) * 64;    // 0 or 64
    const int wn   = (warp & 3) * 32;     // 0,32,64,96
    const int g    = lane >> 3, r7 = lane & 7;

    const uint32_t sb = s2u(sbuf);

    // per-lane ldmatrix base addresses (stage 0)
    uint32_t aA[4], aB[2];
#pragma unroll
    for (int t = 0; t < 4; t++)
        aA[t] = sb + (uint32_t)(wm + 16 * t + (g & 1) * 8 + r7) * 128;
#pragma unroll
    for (int t = 0; t < 2; t++)
        aB[t] = sb + 16384 + (uint32_t)(wn + 16 * t + (g >> 1) * 8 + r7) * 128;

    float acc[4][4][4];
#pragma unroll
    for (int t = 0; t < 4; t++)
#pragma unroll
        for (int nb = 0; nb < 4; nb++)
#pragma unroll
            for (int j = 0; j < 4; j++) acc[t][nb][j] = 0.f;

    // prologue: stage chunks 0 and 1
    stage_chunk_h(Ah, Wh, m0, n0, 0, sb, tid);
    cpa_commit();
    stage_chunk_h(Ah, Wh, m0, n0, 1, sb + 32768, tid);
    cpa_commit();

#pragma unroll 1
    for (int c = 0; c < 4; c++) {
        cpa_wait1();
        __syncthreads();

        const uint32_t soff = (uint32_t)(c & 1) * 32768;
#pragma unroll
        for (int s = 0; s < 4; s++) {
            const uint32_t offA = (uint32_t)(((2 * s + (g >> 1)) ^ r7) << 4) + soff;
            const uint32_t offB = (uint32_t)(((2 * s + (g & 1)) ^ r7) << 4) + soff;
            uint4 a0 = ldsm4(aA[0] + offA);
            uint4 a1 = ldsm4(aA[1] + offA);
            uint4 a2 = ldsm4(aA[2] + offA);
            uint4 a3 = ldsm4(aA[3] + offA);
            uint4 b0 = ldsm4(aB[0] + offB);   // n blocks wn, wn+8
            uint4 b1 = ldsm4(aB[1] + offB);   // n blocks wn+16, wn+24
            mma_f16(acc[0][0], a0, b0.x, b0.y);
            mma_f16(acc[0][1], a0, b0.z, b0.w);
            mma_f16(acc[0][2], a0, b1.x, b1.y);
            mma_f16(acc[0][3], a0, b1.z, b1.w);
            mma_f16(acc[1][0], a1, b0.x, b0.y);
            mma_f16(acc[1][1], a1, b0.z, b0.w);
            mma_f16(acc[1][2], a1, b1.x, b1.y);
            mma_f16(acc[1][3], a1, b1.z, b1.w);
            mma_f16(acc[2][0], a2, b0.x, b0.y);
            mma_f16(acc[2][1], a2, b0.z, b0.w);
            mma_f16(acc[2][2], a2, b1.x, b1.y);
            mma_f16(acc[2][3], a2, b1.z, b1.w);
            mma_f16(acc[3][0], a3, b0.x, b0.y);
            mma_f16(acc[3][1], a3, b0.z, b0.w);
            mma_f16(acc[3][2], a3, b1.x, b1.y);
            mma_f16(acc[3][3], a3, b1.z, b1.w);
        }
        __syncthreads();

        if (c + 2 < 4)
            stage_chunk_h(Ah, Wh, m0, n0, c + 2,
                          sb + (uint32_t)(c & 1) * 32768, tid);
        cpa_commit();   // uniform group accounting
    }

    // epilogue: + bias, write fp32
#pragma unroll
    for (int t = 0; t < 4; t++) {
#pragma unroll
        for (int nb = 0; nb < 4; nb++) {
            int r = m0 + wm + t * 16 + qr;
            int cc = n0 + wn + nb * 8 + qc * 2;
            float b0 = bias[cc], b1 = bias[cc + 1];
            float2 o0 = make_float2(acc[t][nb][0] + b0, acc[t][nb][1] + b1);
            float2 o1 = make_float2(acc[t][nb][2] + b0, acc[t][nb][3] + b1);
            *reinterpret_cast<float2*>(&Out[(size_t)r * N + cc])       = o0;
            *reinterpret_cast<float2*>(&Out[(size_t)(r + 8) * N + cc]) = o1;
        }
    }
}

__global__ void __launch_bounds__(256, 2) qkv_gemm_kernel(
    const float* __restrict__ qkv_b)
{
    gemm_f16_body(g_xh, g_wqkvh, qkv_b, g_qkv, N3);
}

__global__ void __launch_bounds__(256, 2) out_gemm_kernel(
    const float* __restrict__ out_b, float* __restrict__ out)
{
    gemm_f16_body(g_ctxh, g_wouth, out_b, out, CDIM);
}

// ---------------------------------------------------------------------------
// Tensor-core window attention (R5), epilogue writes fp16 ctx.
// ---------------------------------------------------------------------------
#define WBUF_WORDS 6144          // per-warp: Q 2048 | K 2048 | VT 2048
#define SM_MASK_OFF (4 * WBUF_WORDS * 4)           // 98304
#define SM_REL_OFF  (SM_MASK_OFF + 64 * 56 * 2)    // 105472
#define SMEM_ATTN   (SM_REL_OFF + 64 * 56)         // 109056

__global__ void __launch_bounds__(128) win_attn_kernel(
    const float* __restrict__ mask, const float* __restrict__ rpe,
    const int* __restrict__ rel_index)
{
    extern __shared__ __align__(16) char smem[];

    const int w    = blockIdx.x;
    const int tid  = threadIdx.x;
    const int lane = tid & 31;
    const int warp = tid >> 5;
    const int qr   = lane >> 2, qc = lane & 3;
    const int g    = lane >> 3, r7 = lane & 7;
    const float scale = 0.1767766952966369f; // 32^-0.5

    unsigned* wbuf = reinterpret_cast<unsigned*>(smem) + warp * WBUF_WORDS;
    unsigned* Qw  = wbuf;
    unsigned* Kw  = wbuf + 2048;
    unsigned* VTw = wbuf + 4096;
    __nv_bfloat16* smask = reinterpret_cast<__nv_bfloat16*>(smem + SM_MASK_OFF);
    uint8_t*       srel  = reinterpret_cast<uint8_t*>(smem + SM_REL_OFF);

    const uint32_t qb = s2u(Qw), kb = s2u(Kw), vb = s2u(VTw);

    const float* mw = mask + (size_t)(w & 63) * NTOK * NTOK;
    for (int idx = tid; idx < 64 * 56; idx += 128) {
        int n = idx / 56, m = idx - n * 56;
        bool v = (n < NTOK) && (m < NTOK);
        smask[idx] = __float2bfloat16(v ? mw[n * NTOK + m] : 0.f);
        srel[idx]  = v ? (uint8_t)rel_index[n * NTOK + m] : (uint8_t)0;
    }
    __syncthreads();

    const float* base0 = g_qkv + (size_t)w * NTOK * N3;

#pragma unroll 1
    for (int hi = 0; hi < 2; hi++) {
        const int h = warp + hi * 4;
        const float* qbase = base0 + h * HD;

        __syncwarp();
        for (int i = lane; i < 512; i += 32)
            *reinterpret_cast<uint4*>(&VTw[i * 4]) = make_uint4(0, 0, 0, 0);

        for (int it = lane; it < NTOK * 8; it += 32) {
            int n = it >> 3, c4 = (it & 7) << 2;
            const float* r = qbase + (size_t)n * N3 + c4;
            float4 vq = *reinterpret_cast<const float4*>(r);
            float4 vk = *reinterpret_cast<const float4*>(r + CDIM);
            int off = n * 32 + ((c4 >> 2) ^ (n & 7)) * 4;
            *reinterpret_cast<uint4*>(&Qw[off]) =
                make_uint4(f2tf(vq.x * scale), f2tf(vq.y * scale),
                           f2tf(vq.z * scale), f2tf(vq.w * scale));
            *reinterpret_cast<uint4*>(&Kw[off]) =
                make_uint4(f2tf(vk.x), f2tf(vk.y), f2tf(vk.z), f2tf(vk.w));
        }
        for (int it = lane; it < NTOK * 8; it += 32) {
            int m = it >> 3, d4 = (it & 7) << 2;
            float4 vv = *reinterpret_cast<const float4*>(
                qbase + (size_t)m * N3 + 2 * CDIM + d4);
            float e[4] = {vv.x, vv.y, vv.z, vv.w};
#pragma unroll
            for (int ee = 0; ee < 4; ee++) {
                int d = d4 + ee;
                VTw[d * 64 + (((m >> 2) ^ (d & 7)) << 2) + (m & 3)] = f2tf(e[ee]);
            }
        }
        __syncwarp();

#pragma unroll 1
        for (int half = 0; half < 2; half++) {
            float acc[2][8][4];
#pragma unroll
            for (int mt = 0; mt < 2; mt++)
#pragma unroll
                for (int nt = 0; nt < 8; nt++)
#pragma unroll
                    for (int j = 0; j < 4; j++) acc[mt][nt][j] = 0.f;

#pragma unroll
            for (int ks = 0; ks < 4; ks++) {
                uint4 af[2];
#pragma unroll
                for (int mt = 0; mt < 2; mt++) {
                    int row = half * 32 + mt * 16 + (g & 1) * 8 + r7;
                    af[mt] = ldsm4(qb + row * 128 +
                                   (((2 * ks + (g >> 1)) ^ r7) << 4));
                }
#pragma unroll
                for (int p = 0; p < 4; p++) {
                    int rowb = p * 16 + (g >> 1) * 8 + r7;
                    uint4 bb = ldsm4(kb + rowb * 128 +
                                     (((2 * ks + (g & 1)) ^ r7) << 4));
#pragma unroll
                    for (int mt = 0; mt < 2; mt++) {
                        mma_tf32(acc[mt][2 * p],     af[mt], bb.x, bb.y);
                        mma_tf32(acc[mt][2 * p + 1], af[mt], bb.z, bb.w);
                    }
                }
            }

#pragma unroll
            for (int mt = 0; mt < 2; mt++) {
                int r0 = half * 32 + mt * 16 + qr;
                int r1 = r0 + 8;
#pragma unroll
                for (int nt = 0; nt < 8; nt++) {
                    int m0 = nt * 8 + 2 * qc;
                    if (m0 < NTOK) {
                        float b0a = __bfloat162float(smask[r0 * 56 + m0])
                                  + rpe[(int)srel[r0 * 56 + m0] * HEADS_N + h];
                        float b0b = __bfloat162float(smask[r1 * 56 + m0])
                                  + rpe[(int)srel[r1 * 56 + m0] * HEADS_N + h];
                        acc[mt][nt][0] += b0a;
                        acc[mt][nt][2] += b0b;
                    } else {
                        acc[mt][nt][0] = -1e30f;
                        acc[mt][nt][2] = -1e30f;
                    }
                    int m1 = m0 + 1;
                    if (m1 < NTOK) {
                        float b1a = __bfloat162float(smask[r0 * 56 + m1])
                                  + rpe[(int)srel[r0 * 56 + m1] * HEADS_N + h];
                        float b1b = __bfloat162float(smask[r1 * 56 + m1])
                                  + rpe[(int)srel[r1 * 56 + m1] * HEADS_N + h];
                        acc[mt][nt][1] += b1a;
                        acc[mt][nt][3] += b1b;
                    } else {
                        acc[mt][nt][1] = -1e30f;
                        acc[mt][nt][3] = -1e30f;
                    }
                }
            }

#pragma unroll
            for (int mt = 0; mt < 2; mt++) {
                float mx0 = -1e30f, mx1 = -1e30f;
#pragma unroll
                for (int nt = 0; nt < 8; nt++) {
                    mx0 = fmaxf(mx0, fmaxf(acc[mt][nt][0], acc[mt][nt][1]));
                    mx1 = fmaxf(mx1, fmaxf(acc[mt][nt][2], acc[mt][nt][3]));
                }
#pragma unroll
                for (int o = 1; o < 4; o <<= 1) {
                    mx0 = fmaxf(mx0, __shfl_xor_sync(0xffffffffu, mx0, o));
                    mx1 = fmaxf(mx1, __shfl_xor_sync(0xffffffffu, mx1, o));
                }
                float s0 = 0.f, s1 = 0.f;
#pragma unroll
                for (int nt = 0; nt < 8; nt++) {
                    acc[mt][nt][0] = __expf(acc[mt][nt][0] - mx0);
                    acc[mt][nt][1] = __expf(acc[mt][nt][1] - mx0);
                    acc[mt][nt][2] = __expf(acc[mt][nt][2] - mx1);
                    acc[mt][nt][3] = __expf(acc[mt][nt][3] - mx1);
                    s0 += acc[mt][nt][0] + acc[mt][nt][1];
                    s1 += acc[mt][nt][2] + acc[mt][nt][3];
                }
#pragma unroll
                for (int o = 1; o < 4; o <<= 1) {
                    s0 += __shfl_xor_sync(0xffffffffu, s0, o);
                    s1 += __shfl_xor_sync(0xffffffffu, s1, o);
                }
                float i0 = 1.f / s0, i1 = 1.f / s1;
#pragma unroll
                for (int nt = 0; nt < 8; nt++) {
                    acc[mt][nt][0] *= i0; acc[mt][nt][1] *= i0;
                    acc[mt][nt][2] *= i1; acc[mt][nt][3] *= i1;
                }
            }

            float cacc[2][4][4];
#pragma unroll
            for (int mt = 0; mt < 2; mt++)
#pragma unroll
                for (int dt = 0; dt < 4; dt++)
#pragma unroll
                    for (int j = 0; j < 4; j++) cacc[mt][dt][j] = 0.f;

            const int sbase = lane & ~3;
            const int sL = sbase + (qc >> 1);
            const int sH = sL + 2;
            const bool podd = qc & 1;

#pragma unroll
            for (int j = 0; j < 8; j++) {
                uint4 aP[2];
#pragma unroll
                for (int mt = 0; mt < 2; mt++) {
                    float c0 = acc[mt][j][0], c1 = acc[mt][j][1];
                    float c2 = acc[mt][j][2], c3 = acc[mt][j][3];
                    float t0 = __shfl_sync(0xffffffffu, c0, sL);
                    float t1 = __shfl_sync(0xffffffffu, c1, sL);
                    float u0 = __shfl_sync(0xffffffffu, c0, sH);
                    float u1 = __shfl_sync(0xffffffffu, c1, sH);
                    float v0 = __shfl_sync(0xffffffffu, c2, sL);
                    float v1 = __shfl_sync(0xffffffffu, c3, sL);
                    float w0 = __shfl_sync(0xffffffffu, c2, sH);
                    float w1 = __shfl_sync(0xffffffffu, c3, sH);
                    aP[mt].x = f2tf(podd ? t1 : t0);
                    aP[mt].y = f2tf(podd ? v1 : v0);
                    aP[mt].z = f2tf(podd ? u1 : u0);
                    aP[mt].w = f2tf(podd ? w1 : w0);
                }
                uint32_t voff = (((2 * j + (g & 1)) ^ r7) << 4);
                uint4 b0 = ldsm4(vb + ((g >> 1) * 8 + r7) * 256 + voff);
                uint4 b1 = ldsm4(vb + (16 + (g >> 1) * 8 + r7) * 256 + voff);
#pragma unroll
                for (int mt = 0; mt < 2; mt++) {
                    mma_tf32(cacc[mt][0], aP[mt], b0.x, b0.y);
                    mma_tf32(cacc[mt][1], aP[mt], b0.z, b0.w);
                    mma_tf32(cacc[mt][2], aP[mt], b1.x, b1.y);
                    mma_tf32(cacc[mt][3], aP[mt], b1.z, b1.w);
                }
            }

            // store ctx as fp16 (feeds the fp16 out-GEMM)
#pragma unroll
            for (int mt = 0; mt < 2; mt++) {
                int n0 = half * 32 + mt * 16 + qr;
#pragma unroll
                for (int dt = 0; dt < 4; dt++) {
                    int col = h * HD + dt * 8 + 2 * qc;
                    if (n0 < NTOK)
                        *reinterpret_cast<uint32_t*>(
                            &g_ctxh[((size_t)w * NTOK + n0) * CDIM + col]) =
                            f2h2(cacc[mt][dt][0], cacc[mt][dt][1]);
                    if (n0 + 8 < NTOK)
                        *reinterpret_cast<uint32_t*>(
                            &g_ctxh[((size_t)w * NTOK + n0 + 8) * CDIM + col]) =
                            f2h2(cacc[mt][dt][2], cacc[mt][dt][3]);
                }
            }
        }
    }
}

// ---------------------------------------------------------------------------
extern "C" void kernel_launch(void* const* d_in, const int* in_sizes, int n_in,
                              void* d_out, int out_size)
{
    const float* x     = (const float*)d_in[0];
    const float* mask  = (const float*)d_in[1];
    const float* qkv_w = (const float*)d_in[2];
    const float* qkv_b = (const float*)d_in[3];
    const float* rpe   = (const float*)d_in[4];
    const float* out_w = (const float*)d_in[5];
    const float* out_b = (const float*)d_in[6];
    const int*   rel   = (const int*)d_in[7];
    float* out = (float*)d_out;

    cudaFuncSetAttribute(win_attn_kernel,
                         cudaFuncAttributeMaxDynamicSharedMemorySize, SMEM_ATTN);

    // prepass: fp16 conversions
    cvt_x_kernel<<<(MROWS * CDIM / 4) / 256, 256>>>(x);
    cvt_w_kernel<<<((N3 * CDIM + CDIM * CDIM) / 4) / 256, 256>>>(qkv_w, out_w);

    dim3 g1(N3 / 128, MROWS / 128);   // 6 x 1568
    qkv_gemm_kernel<<<g1, 256>>>(qkv_b);

    win_attn_kernel<<<NWIN, 128, SMEM_ATTN>>>(mask, rpe, rel);

    dim3 g3(CDIM / 128, MROWS / 128); // 2 x 1568
    out_gemm_kernel<<<g3, 256>>>(out_b, out);
}

// round 8
// speedup vs baseline: 5.4671x; 1.2145x over previous
#include <cuda_runtime.h>
#include <cuda_fp16.h>
#include <cuda_bf16.h>
#include <cstdint>

// ---------------------------------------------------------------------------
// ShiftedWindowAttention (Swin window-MSA) — all-fp16 tensor-core pipeline
//   Stage 0: x / weights -> fp16
//   Stage 1: qkv GEMM (fp16 in/out, fp32 accum; q pre-scaled in epilogue)
//   Stage 2: window attention, warp = (window, head), fp16 mma m16n8k16
//   Stage 3: out GEMM (fp16 in, fp32 out)
// ---------------------------------------------------------------------------

#define NWIN    4096
#define NTOK    49
#define CDIM    256
#define HEADS_N 8
#define HD      32
#define MROWS   (NWIN * NTOK)    // 200704
#define N3      (3 * CDIM)       // 768
#define QSCALE  0.1767766952966369f

__device__ __half g_qkvh[(size_t)MROWS * N3];   // (M, 768) fp16, q pre-scaled
__device__ __half g_xh[(size_t)MROWS * CDIM];   // x as fp16
__device__ __half g_ctxh[(size_t)MROWS * CDIM]; // ctx as fp16
__device__ __half g_wqkvh[N3 * CDIM];           // qkv_w as fp16
__device__ __half g_wouth[CDIM * CDIM];         // out_w as fp16

// ---------------------------------------------------------------------------
// helpers
// ---------------------------------------------------------------------------
__device__ __forceinline__ uint32_t f2h2(float lo, float hi) {
    uint32_t u;
    asm("cvt.rn.f16x2.f32 %0, %1, %2;" : "=r"(u) : "f"(hi), "f"(lo));
    return u;
}

__device__ __forceinline__ uint32_t s2u(const void* p) {
    return (uint32_t)__cvta_generic_to_shared(p);
}

__device__ __forceinline__ uint4 ldsm4(uint32_t a) {
    uint4 r;
    asm volatile("ldmatrix.sync.aligned.m8n8.x4.shared.b16 {%0,%1,%2,%3}, [%4];"
                 : "=r"(r.x), "=r"(r.y), "=r"(r.z), "=r"(r.w) : "r"(a));
    return r;
}

__device__ __forceinline__ uint4 ldsm4t(uint32_t a) {
    uint4 r;
    asm volatile("ldmatrix.sync.aligned.m8n8.x4.trans.shared.b16 {%0,%1,%2,%3}, [%4];"
                 : "=r"(r.x), "=r"(r.y), "=r"(r.z), "=r"(r.w) : "r"(a));
    return r;
}

__device__ __forceinline__ void cpa16(uint32_t dst, const void* src) {
    asm volatile("cp.async.cg.shared.global [%0], [%1], 16;"
                 :: "r"(dst), "l"(src));
}
__device__ __forceinline__ void cpa_commit() {
    asm volatile("cp.async.commit_group;");
}
__device__ __forceinline__ void cpa_wait1() {
    asm volatile("cp.async.wait_group 1;");
}

__device__ __forceinline__ void mma_f16(float* c, const uint4& a,
                                        unsigned b0, unsigned b1) {
    asm volatile(
        "mma.sync.aligned.m16n8k16.row.col.f32.f16.f16.f32 "
        "{%0,%1,%2,%3}, {%4,%5,%6,%7}, {%8,%9}, {%0,%1,%2,%3};"
        : "+f"(c[0]), "+f"(c[1]), "+f"(c[2]), "+f"(c[3])
        : "r"(a.x), "r"(a.y), "r"(a.z), "r"(a.w), "r"(b0), "r"(b1));
}

// ---------------------------------------------------------------------------
// prepass: fp32 -> fp16
// ---------------------------------------------------------------------------
__global__ void __launch_bounds__(256) cvt_x_kernel(const float* __restrict__ x)
{
    int i = blockIdx.x * 256 + threadIdx.x;
    float4 v = reinterpret_cast<const float4*>(x)[i];
    reinterpret_cast<uint2*>(g_xh)[i] =
        make_uint2(f2h2(v.x, v.y), f2h2(v.z, v.w));
}

__global__ void __launch_bounds__(256) cvt_w_kernel(
    const float* __restrict__ qkv_w, const float* __restrict__ out_w)
{
    int i = blockIdx.x * 256 + threadIdx.x;
    if (i < (N3 * CDIM) / 4) {
        float4 v = reinterpret_cast<const float4*>(qkv_w)[i];
        reinterpret_cast<uint2*>(g_wqkvh)[i] =
            make_uint2(f2h2(v.x, v.y), f2h2(v.z, v.w));
    } else {
        int j = i - (N3 * CDIM) / 4;
        float4 v = reinterpret_cast<const float4*>(out_w)[j];
        reinterpret_cast<uint2*>(g_wouth)[j] =
            make_uint2(f2h2(v.x, v.y), f2h2(v.z, v.w));
    }
}

// ---------------------------------------------------------------------------
// fp16 GEMM:  Out[m,n] = sum_k A[m,k] * W[n,k] + bias[n]   (K = 256)
// Block 128x128, 8 warps (2m x 4n), warp tile 64x32, chunk = 64 halves,
// 2-stage cp.async double buffer. HALF_OUT: fp16 output (+ q-scale cols<256).
// ---------------------------------------------------------------------------
#define GEMM_SMEM 65536

__device__ __forceinline__ void stage_chunk_h(
    const __half* __restrict__ Ah, const __half* __restrict__ Wh,
    int m0, int n0, int c, uint32_t dstbase, int tid)
{
    const int rr   = tid >> 1;
    const int segb = (tid & 1) * 4;
    const char* As = reinterpret_cast<const char*>(Ah) +
                     (size_t)(m0 + rr) * 512 + c * 128;
    const char* Ws = reinterpret_cast<const char*>(Wh) +
                     (size_t)(n0 + rr) * 512 + c * 128;
    const uint32_t drow = dstbase + rr * 128;
#pragma unroll
    for (int i = 0; i < 4; i++) {
        int seg = segb + i;
        uint32_t d = drow + ((seg ^ (rr & 7)) << 4);
        cpa16(d,         As + seg * 16);
        cpa16(d + 16384, Ws + seg * 16);
    }
}

template <bool HALF_OUT, bool SCALE_Q>
__device__ __forceinline__ void gemm_f16_body(
    const __half* __restrict__ Ah, const __half* __restrict__ Wh,
    const float* __restrict__ bias, void* __restrict__ OutP, int N)
{
    __shared__ __align__(16) char sbuf[GEMM_SMEM];

    const int tid  = threadIdx.x;
    const int m0   = blockIdx.y * 128;
    const int n0   = blockIdx.x * 128;
    const int warp = tid >> 5, lane = tid & 31;
    const int qr   = lane >> 2, qc = lane & 3;
    const int wm   = (warp >> 2) * 64;
    const int wn   = (warp & 3) * 32;
    const int g    = lane >> 3, r7 = lane & 7;

    const uint32_t sb = s2u(sbuf);

    uint32_t aA[4], aB[2];
#pragma unroll
    for (int t = 0; t < 4; t++)
        aA[t] = sb + (uint32_t)(wm + 16 * t + (g & 1) * 8 + r7) * 128;
#pragma unroll
    for (int t = 0; t < 2; t++)
        aB[t] = sb + 16384 + (uint32_t)(wn + 16 * t + (g >> 1) * 8 + r7) * 128;

    float acc[4][4][4];
#pragma unroll
    for (int t = 0; t < 4; t++)
#pragma unroll
        for (int nb = 0; nb < 4; nb++)
#pragma unroll
            for (int j = 0; j < 4; j++) acc[t][nb][j] = 0.f;

    stage_chunk_h(Ah, Wh, m0, n0, 0, sb, tid);
    cpa_commit();
    stage_chunk_h(Ah, Wh, m0, n0, 1, sb + 32768, tid);
    cpa_commit();

#pragma unroll 1
    for (int c = 0; c < 4; c++) {
        cpa_wait1();
        __syncthreads();

        const uint32_t soff = (uint32_t)(c & 1) * 32768;
#pragma unroll
        for (int s = 0; s < 4; s++) {
            const uint32_t offA = (uint32_t)(((2 * s + (g >> 1)) ^ r7) << 4) + soff;
            const uint32_t offB = (uint32_t)(((2 * s + (g & 1)) ^ r7) << 4) + soff;
            uint4 a0 = ldsm4(aA[0] + offA);
            uint4 a1 = ldsm4(aA[1] + offA);
            uint4 a2 = ldsm4(aA[2] + offA);
            uint4 a3 = ldsm4(aA[3] + offA);
            uint4 b0 = ldsm4(aB[0] + offB);
            uint4 b1 = ldsm4(aB[1] + offB);
            mma_f16(acc[0][0], a0, b0.x, b0.y);
            mma_f16(acc[0][1], a0, b0.z, b0.w);
            mma_f16(acc[0][2], a0, b1.x, b1.y);
            mma_f16(acc[0][3], a0, b1.z, b1.w);
            mma_f16(acc[1][0], a1, b0.x, b0.y);
            mma_f16(acc[1][1], a1, b0.z, b0.w);
            mma_f16(acc[1][2], a1, b1.x, b1.y);
            mma_f16(acc[1][3], a1, b1.z, b1.w);
            mma_f16(acc[2][0], a2, b0.x, b0.y);
            mma_f16(acc[2][1], a2, b0.z, b0.w);
            mma_f16(acc[2][2], a2, b1.x, b1.y);
            mma_f16(acc[2][3], a2, b1.z, b1.w);
            mma_f16(acc[3][0], a3, b0.x, b0.y);
            mma_f16(acc[3][1], a3, b0.z, b0.w);
            mma_f16(acc[3][2], a3, b1.x, b1.y);
            mma_f16(acc[3][3], a3, b1.z, b1.w);
        }
        __syncthreads();

        if (c + 2 < 4)
            stage_chunk_h(Ah, Wh, m0, n0, c + 2,
                          sb + (uint32_t)(c & 1) * 32768, tid);
        cpa_commit();
    }

#pragma unroll
    for (int t = 0; t < 4; t++) {
#pragma unroll
        for (int nb = 0; nb < 4; nb++) {
            int r = m0 + wm + t * 16 + qr;
            int cc = n0 + wn + nb * 8 + qc * 2;
            float b0 = bias[cc], b1 = bias[cc + 1];
            if (HALF_OUT) {
                float sc = (SCALE_Q && cc < 256) ? QSCALE : 1.f;
                __half* Oh = (__half*)OutP;
                *reinterpret_cast<uint32_t*>(&Oh[(size_t)r * N + cc]) =
                    f2h2((acc[t][nb][0] + b0) * sc, (acc[t][nb][1] + b1) * sc);
                *reinterpret_cast<uint32_t*>(&Oh[(size_t)(r + 8) * N + cc]) =
                    f2h2((acc[t][nb][2] + b0) * sc, (acc[t][nb][3] + b1) * sc);
            } else {
                float* Of = (float*)OutP;
                *reinterpret_cast<float2*>(&Of[(size_t)r * N + cc]) =
                    make_float2(acc[t][nb][0] + b0, acc[t][nb][1] + b1);
                *reinterpret_cast<float2*>(&Of[(size_t)(r + 8) * N + cc]) =
                    make_float2(acc[t][nb][2] + b0, acc[t][nb][3] + b1);
            }
        }
    }
}

__global__ void __launch_bounds__(256, 2) qkv_gemm_kernel(
    const float* __restrict__ qkv_b)
{
    gemm_f16_body<true, true>(g_xh, g_wqkvh, qkv_b, g_qkvh, N3);
}

__global__ void __launch_bounds__(256, 2) out_gemm_kernel(
    const float* __restrict__ out_b, float* __restrict__ out)
{
    gemm_f16_body<false, false>(g_ctxh, g_wouth, out_b, out, CDIM);
}

// ---------------------------------------------------------------------------
// fp16 window attention. CTA = 256 threads = 8 warps = 1 window; warp = head.
// Per-warp smem (fp16): Q[64][32h] 4KB, K[64][32h] 4KB, V[64][32h] 4KB.
// Q/K rows = 64B = 4 slots of 16B, swizzle: phys = slot ^ ((row>>1)&3).
// S = QK^T (fp16 mma, k=16); bias+mask in acc layout; quad-shuffle softmax;
// P packed straight into A-fragments (layout identity); PV with ldmatrix.trans.
// ---------------------------------------------------------------------------
#define WBYTES 12288
#define SM_MASK_OFF (8 * WBYTES)                   // 98304
#define SM_REL_OFF  (SM_MASK_OFF + 64 * 56 * 2)    // 105472
#define SMEM_ATTN   (SM_REL_OFF + 64 * 56)         // 109056

__global__ void __launch_bounds__(256, 2) win_attn_kernel(
    const float* __restrict__ mask, const float* __restrict__ rpe,
    const int* __restrict__ rel_index)
{
    extern __shared__ __align__(16) char smem[];

    const int w    = blockIdx.x;
    const int tid  = threadIdx.x;
    const int lane = tid & 31;
    const int warp = tid >> 5;       // == head h
    const int h    = warp;
    const int qr   = lane >> 2, qc = lane & 3;
    const int g    = lane >> 3, r7 = lane & 7;

    char* wbuf = smem + warp * WBYTES;
    const uint32_t qb = s2u(wbuf);
    const uint32_t kb = qb + 4096;
    const uint32_t vb = qb + 8192;
    __nv_bfloat16* smask = reinterpret_cast<__nv_bfloat16*>(smem + SM_MASK_OFF);
    uint8_t*       srel  = reinterpret_cast<uint8_t*>(smem + SM_REL_OFF);

    // ---- head-invariant staging: mask (bf16) + rel index (u8), padded ----
    const float* mw = mask + (size_t)(w & 63) * NTOK * NTOK;
    for (int idx = tid; idx < 64 * 56; idx += 256) {
        int n = idx / 56, m = idx - n * 56;
        bool v = (n < NTOK) && (m < NTOK);
        smask[idx] = __float2bfloat16(v ? mw[n * NTOK + m] : 0.f);
        srel[idx]  = v ? (uint8_t)rel_index[n * NTOK + m] : (uint8_t)0;
    }
    __syncthreads();

    // ---- zero V (pad rows must be 0: P=0 x garbage would NaN) ----
    {
        uint4 z = make_uint4(0, 0, 0, 0);
        for (int i = lane; i < 256; i += 32)
            *reinterpret_cast<uint4*>(wbuf + 8192 + i * 16) = z;
    }
    __syncwarp();

    // ---- stage Q, K, V rows (q pre-scaled in qkv epilogue) ----
    {
        const __half* hb = g_qkvh + (size_t)w * NTOK * N3 + h * HD;
        for (int it = lane; it < NTOK * 4; it += 32) {
            int r = it >> 2, s = it & 3;
            const __half* src = hb + (size_t)r * N3 + s * 8;
            uint32_t doff = r * 64 + ((s ^ ((r >> 1) & 3)) << 4);
            uint4 vq = *reinterpret_cast<const uint4*>(src);
            uint4 vk = *reinterpret_cast<const uint4*>(src + CDIM);
            uint4 vv = *reinterpret_cast<const uint4*>(src + 2 * CDIM);
            *reinterpret_cast<uint4*>(wbuf + doff)        = vq;
            *reinterpret_cast<uint4*>(wbuf + 4096 + doff) = vk;
            *reinterpret_cast<uint4*>(wbuf + 8192 + doff) = vv;
        }
    }
    __syncwarp();

#pragma unroll 1
    for (int half = 0; half < 2; half++) {
        const int mb = half * 32;

        // ---- S = Q K^T ----
        float acc[2][8][4];
#pragma unroll
        for (int mt = 0; mt < 2; mt++)
#pragma unroll
            for (int nt = 0; nt < 8; nt++)
#pragma unroll
                for (int j = 0; j < 4; j++) acc[mt][nt][j] = 0.f;

#pragma unroll
        for (int s = 0; s < 2; s++) {
            uint4 af[2];
#pragma unroll
            for (int mt = 0; mt < 2; mt++) {
                int row  = mb + mt * 16 + (g & 1) * 8 + r7;
                int slot = 2 * s + (g >> 1);
                af[mt] = ldsm4(qb + row * 64 + ((slot ^ ((row >> 1) & 3)) << 4));
            }
#pragma unroll
            for (int p = 0; p < 4; p++) {
                int row  = p * 16 + (g >> 1) * 8 + r7;
                int slot = 2 * s + (g & 1);
                uint4 bb = ldsm4(kb + row * 64 + ((slot ^ ((row >> 1) & 3)) << 4));
#pragma unroll
                for (int mt = 0; mt < 2; mt++) {
                    mma_f16(acc[mt][2 * p],     af[mt], bb.x, bb.y);
                    mma_f16(acc[mt][2 * p + 1], af[mt], bb.z, bb.w);
                }
            }
        }

        // ---- bias + mask (cols >= 49 -> -1e30) ----
#pragma unroll
        for (int mt = 0; mt < 2; mt++) {
            int r0 = mb + mt * 16 + qr;
            int r1 = r0 + 8;
#pragma unroll
            for (int nt = 0; nt < 8; nt++) {
                int m0 = nt * 8 + 2 * qc;
                if (m0 < NTOK) {
                    acc[mt][nt][0] += __bfloat162float(smask[r0 * 56 + m0])
                                    + rpe[(int)srel[r0 * 56 + m0] * HEADS_N + h];
                    acc[mt][nt][2] += __bfloat162float(smask[r1 * 56 + m0])
                                    + rpe[(int)srel[r1 * 56 + m0] * HEADS_N + h];
                } else {
                    acc[mt][nt][0] = -1e30f;
                    acc[mt][nt][2] = -1e30f;
                }
                int m1 = m0 + 1;
                if (m1 < NTOK) {
                    acc[mt][nt][1] += __bfloat162float(smask[r0 * 56 + m1])
                                    + rpe[(int)srel[r0 * 56 + m1] * HEADS_N + h];
                    acc[mt][nt][3] += __bfloat162float(smask[r1 * 56 + m1])
                                    + rpe[(int)srel[r1 * 56 + m1] * HEADS_N + h];
                } else {
                    acc[mt][nt][1] = -1e30f;
                    acc[mt][nt][3] = -1e30f;
                }
            }
        }

        // ---- softmax (rows spread over quad lanes) ----
#pragma unroll
        for (int mt = 0; mt < 2; mt++) {
            float mx0 = -1e30f, mx1 = -1e30f;
#pragma unroll
            for (int nt = 0; nt < 8; nt++) {
                mx0 = fmaxf(mx0, fmaxf(acc[mt][nt][0], acc[mt][nt][1]));
                mx1 = fmaxf(mx1, fmaxf(acc[mt][nt][2], acc[mt][nt][3]));
            }
#pragma unroll
            for (int o = 1; o < 4; o <<= 1) {
                mx0 = fmaxf(mx0, __shfl_xor_sync(0xffffffffu, mx0, o));
                mx1 = fmaxf(mx1, __shfl_xor_sync(0xffffffffu, mx1, o));
            }
            float s0 = 0.f, s1 = 0.f;
#pragma unroll
            for (int nt = 0; nt < 8; nt++) {
                acc[mt][nt][0] = __expf(acc[mt][nt][0] - mx0);
                acc[mt][nt][1] = __expf(acc[mt][nt][1] - mx0);
                acc[mt][nt][2] = __expf(acc[mt][nt][2] - mx1);
                acc[mt][nt][3] = __expf(acc[mt][nt][3] - mx1);
                s0 += acc[mt][nt][0] + acc[mt][nt][1];
                s1 += acc[mt][nt][2] + acc[mt][nt][3];
            }
#pragma unroll
            for (int o = 1; o < 4; o <<= 1) {
                s0 += __shfl_xor_sync(0xffffffffu, s0, o);
                s1 += __shfl_xor_sync(0xffffffffu, s1, o);
            }
            float i0 = 1.f / s0, i1 = 1.f / s1;
#pragma unroll
            for (int nt = 0; nt < 8; nt++) {
                acc[mt][nt][0] *= i0; acc[mt][nt][1] *= i0;
                acc[mt][nt][2] *= i1; acc[mt][nt][3] *= i1;
            }
        }

        // ---- C = P V  (P packs directly into A-fragments; V via ldsm.trans)
        float cacc[2][4][4];
#pragma unroll
        for (int mt = 0; mt < 2; mt++)
#pragma unroll
            for (int dt = 0; dt < 4; dt++)
#pragma unroll
                for (int j = 0; j < 4; j++) cacc[mt][dt][j] = 0.f;

#pragma unroll
        for (int j = 0; j < 4; j++) {
            uint4 aP[2];
#pragma unroll
            for (int mt = 0; mt < 2; mt++) {
                aP[mt].x = f2h2(acc[mt][2 * j][0],     acc[mt][2 * j][1]);
                aP[mt].y = f2h2(acc[mt][2 * j][2],     acc[mt][2 * j][3]);
                aP[mt].z = f2h2(acc[mt][2 * j + 1][0], acc[mt][2 * j + 1][1]);
                aP[mt].w = f2h2(acc[mt][2 * j + 1][2], acc[mt][2 * j + 1][3]);
            }
#pragma unroll
            for (int dp = 0; dp < 2; dp++) {
                int row  = 16 * j + (g & 1) * 8 + r7;
                int slot = 2 * dp + (g >> 1);
                uint4 bb = ldsm4t(vb + row * 64 + ((slot ^ ((row >> 1) & 3)) << 4));
#pragma unroll
                for (int mt = 0; mt < 2; mt++) {
                    mma_f16(cacc[mt][2 * dp],     aP[mt], bb.x, bb.y);
                    mma_f16(cacc[mt][2 * dp + 1], aP[mt], bb.z, bb.w);
                }
            }
        }

        // ---- store ctx (fp16) ----
#pragma unroll
        for (int mt = 0; mt < 2; mt++) {
            int n0 = mb + mt * 16 + qr;
#pragma unroll
            for (int dt = 0; dt < 4; dt++) {
                int col = h * HD + dt * 8 + 2 * qc;
                if (n0 < NTOK)
                    *reinterpret_cast<uint32_t*>(
                        &g_ctxh[((size_t)w * NTOK + n0) * CDIM + col]) =
                        f2h2(cacc[mt][dt][0], cacc[mt][dt][1]);
                if (n0 + 8 < NTOK)
                    *reinterpret_cast<uint32_t*>(
                        &g_ctxh[((size_t)w * NTOK + n0 + 8) * CDIM + col]) =
                        f2h2(cacc[mt][dt][2], cacc[mt][dt][3]);
            }
        }
    }
}

// ---------------------------------------------------------------------------
extern "C" void kernel_launch(void* const* d_in, const int* in_sizes, int n_in,
                              void* d_out, int out_size)
{
    const float* x     = (const float*)d_in[0];
    const float* mask  = (const float*)d_in[1];
    const float* qkv_w = (const float*)d_in[2];
    const float* qkv_b = (const float*)d_in[3];
    const float* rpe   = (const float*)d_in[4];
    const float* out_w = (const float*)d_in[5];
    const float* out_b = (const float*)d_in[6];
    const int*   rel   = (const int*)d_in[7];
    float* out = (float*)d_out;

    cudaFuncSetAttribute(win_attn_kernel,
                         cudaFuncAttributeMaxDynamicSharedMemorySize, SMEM_ATTN);

    cvt_x_kernel<<<(MROWS * CDIM / 4) / 256, 256>>>(x);
    cvt_w_kernel<<<((N3 * CDIM + CDIM * CDIM) / 4) / 256, 256>>>(qkv_w, out_w);

    dim3 g1(N3 / 128, MROWS / 128);   // 6 x 1568
    qkv_gemm_kernel<<<g1, 256>>>(qkv_b);

    win_attn_kernel<<<NWIN, 256, SMEM_ATTN>>>(mask, rpe, rel);

    dim3 g3(CDIM / 128, MROWS / 128); // 2 x 1568
    out_gemm_kernel<<<g3, 256>>>(out_b, out);
}

// round 10
// speedup vs baseline: 6.6629x; 1.2187x over previous
#include <cuda_runtime.h>
#include <cuda_fp16.h>
#include <cstdint>

// ---------------------------------------------------------------------------
// ShiftedWindowAttention (Swin window-MSA) — all-fp16 tensor-core pipeline
//   Stage 0: x / weights -> fp16; fused (mask + rpe-bias) table build
//   Stage 1: qkv GEMM (fp16 in/out, head-blocked output, q pre-scaled)
//   Stage 2: window attention, warp = (window, head), coalesced cp.async
//            staging, bias-table accumulator init (table m-dim = 64!)
//   Stage 3: out GEMM (fp16 in, fp32 out)
// ---------------------------------------------------------------------------

#define NWIN    4096
#define NTOK    49
#define CDIM    256
#define HEADS_N 8
#define HD      32
#define MROWS   (NWIN * NTOK)    // 200704
#define N3      (3 * CDIM)       // 768
#define QSCALE  0.1767766952966369f

// qkv head-blocked: addr = ((which*8 + h)*MROWS + m)*32 + d
__device__ __half g_qkvh[(size_t)MROWS * N3];
__device__ __half g_xh[(size_t)MROWS * CDIM];
__device__ __half g_ctxh[(size_t)MROWS * CDIM];
__device__ __half g_wqkvh[N3 * CDIM];
__device__ __half g_wouth[CDIM * CDIM];
// fused bias+mask table: [wm 64][h 8][n 64][m 64], pad = -60000
__device__ __align__(16) __half g_bm[64 * 8 * 64 * 64];

// ---------------------------------------------------------------------------
// helpers
// ---------------------------------------------------------------------------
__device__ __forceinline__ uint32_t f2h2(float lo, float hi) {
    uint32_t u;
    asm("cvt.rn.f16x2.f32 %0, %1, %2;" : "=r"(u) : "f"(hi), "f"(lo));
    return u;
}

__device__ __forceinline__ uint32_t s2u(const void* p) {
    return (uint32_t)__cvta_generic_to_shared(p);
}

__device__ __forceinline__ uint4 ldsm4(uint32_t a) {
    uint4 r;
    asm volatile("ldmatrix.sync.aligned.m8n8.x4.shared.b16 {%0,%1,%2,%3}, [%4];"
                 : "=r"(r.x), "=r"(r.y), "=r"(r.z), "=r"(r.w) : "r"(a));
    return r;
}

__device__ __forceinline__ uint4 ldsm4t(uint32_t a) {
    uint4 r;
    asm volatile("ldmatrix.sync.aligned.m8n8.x4.trans.shared.b16 {%0,%1,%2,%3}, [%4];"
                 : "=r"(r.x), "=r"(r.y), "=r"(r.z), "=r"(r.w) : "r"(a));
    return r;
}

__device__ __forceinline__ void cpa16(uint32_t dst, const void* src) {
    asm volatile("cp.async.cg.shared.global [%0], [%1], 16;"
                 :: "r"(dst), "l"(src));
}
__device__ __forceinline__ void cpa_commit() {
    asm volatile("cp.async.commit_group;");
}
__device__ __forceinline__ void cpa_wait1() {
    asm volatile("cp.async.wait_group 1;");
}
__device__ __forceinline__ void cpa_wait0() {
    asm volatile("cp.async.wait_group 0;");
}

__device__ __forceinline__ void mma_f16(float* c, const uint4& a,
                                        unsigned b0, unsigned b1) {
    asm volatile(
        "mma.sync.aligned.m16n8k16.row.col.f32.f16.f16.f32 "
        "{%0,%1,%2,%3}, {%4,%5,%6,%7}, {%8,%9}, {%0,%1,%2,%3};"
        : "+f"(c[0]), "+f"(c[1]), "+f"(c[2]), "+f"(c[3])
        : "r"(a.x), "r"(a.y), "r"(a.z), "r"(a.w), "r"(b0), "r"(b1));
}

// ---------------------------------------------------------------------------
// prepass kernels
// ---------------------------------------------------------------------------
__global__ void __launch_bounds__(256) cvt_x_kernel(const float* __restrict__ x)
{
    int i = blockIdx.x * 256 + threadIdx.x;
    float4 v = reinterpret_cast<const float4*>(x)[i];
    reinterpret_cast<uint2*>(g_xh)[i] =
        make_uint2(f2h2(v.x, v.y), f2h2(v.z, v.w));
}

__global__ void __launch_bounds__(256) cvt_w_kernel(
    const float* __restrict__ qkv_w, const float* __restrict__ out_w)
{
    int i = blockIdx.x * 256 + threadIdx.x;
    if (i < (N3 * CDIM) / 4) {
        float4 v = reinterpret_cast<const float4*>(qkv_w)[i];
        reinterpret_cast<uint2*>(g_wqkvh)[i] =
            make_uint2(f2h2(v.x, v.y), f2h2(v.z, v.w));
    } else {
        int j = i - (N3 * CDIM) / 4;
        float4 v = reinterpret_cast<const float4*>(out_w)[j];
        reinterpret_cast<uint2*>(g_wouth)[j] =
            make_uint2(f2h2(v.x, v.y), f2h2(v.z, v.w));
    }
}

// fused bias table: bm[wm][h][n][m] = mask(wm,n,m) + rpe[rel(n,m)][h], pad -6e4
__global__ void __launch_bounds__(256) build_bm_kernel(
    const float* __restrict__ mask, const float* __restrict__ rpe,
    const int* __restrict__ rel_index)
{
    int idx = blockIdx.x * 256 + threadIdx.x;   // 64*8*64*64 total
    int m  = idx & 63;
    int n  = (idx >> 6) & 63;
    int h  = (idx >> 12) & 7;
    int wm = idx >> 15;
    float v = -60000.f;
    if (n < NTOK && m < NTOK) {
        int nm = n * NTOK + m;
        v = mask[wm * NTOK * NTOK + nm] + rpe[rel_index[nm] * HEADS_N + h];
    }
    g_bm[idx] = __float2half(v);
}

// ---------------------------------------------------------------------------
// fp16 GEMM:  Out[m,n] = sum_k A[m,k] * W[n,k] + bias[n]   (K = 256)
// Block 128x128, 8 warps (2m x 4n), warp tile 64x32, chunk = 64 halves,
// 2-stage cp.async double buffer. HEAD_OUT: fp16 head-blocked out + q scale.
// ---------------------------------------------------------------------------
#define GEMM_SMEM 65536

__device__ __forceinline__ void stage_chunk_h(
    const __half* __restrict__ Ah, const __half* __restrict__ Wh,
    int m0, int n0, int c, uint32_t dstbase, int tid)
{
    const int rr   = tid >> 1;
    const int segb = (tid & 1) * 4;
    const char* As = reinterpret_cast<const char*>(Ah) +
                     (size_t)(m0 + rr) * 512 + c * 128;
    const char* Ws = reinterpret_cast<const char*>(Wh) +
                     (size_t)(n0 + rr) * 512 + c * 128;
    const uint32_t drow = dstbase + rr * 128;
#pragma unroll
    for (int i = 0; i < 4; i++) {
        int seg = segb + i;
        uint32_t d = drow + ((seg ^ (rr & 7)) << 4);
        cpa16(d,         As + seg * 16);
        cpa16(d + 16384, Ws + seg * 16);
    }
}

template <bool HEAD_OUT>
__device__ __forceinline__ void gemm_f16_body(
    const __half* __restrict__ Ah, const __half* __restrict__ Wh,
    const float* __restrict__ bias, void* __restrict__ OutP, int N)
{
    __shared__ __align__(16) char sbuf[GEMM_SMEM];

    const int tid  = threadIdx.x;
    const int m0   = blockIdx.y * 128;
    const int n0   = blockIdx.x * 128;
    const int warp = tid >> 5, lane = tid & 31;
    const int qr   = lane >> 2, qc = lane & 3;
    const int wm   = (warp >> 2) * 64;
    const int wn   = (warp & 3) * 32;
    const int g    = lane >> 3, r7 = lane & 7;

    const uint32_t sb = s2u(sbuf);

    uint32_t aA[4], aB[2];
#pragma unroll
    for (int t = 0; t < 4; t++)
        aA[t] = sb + (uint32_t)(wm + 16 * t + (g & 1) * 8 + r7) * 128;
#pragma unroll
    for (int t = 0; t < 2; t++)
        aB[t] = sb + 16384 + (uint32_t)(wn + 16 * t + (g >> 1) * 8 + r7) * 128;

    float acc[4][4][4];
#pragma unroll
    for (int t = 0; t < 4; t++)
#pragma unroll
        for (int nb = 0; nb < 4; nb++)
#pragma unroll
            for (int j = 0; j < 4; j++) acc[t][nb][j] = 0.f;

    stage_chunk_h(Ah, Wh, m0, n0, 0, sb, tid);
    cpa_commit();
    stage_chunk_h(Ah, Wh, m0, n0, 1, sb + 32768, tid);
    cpa_commit();

#pragma unroll 1
    for (int c = 0; c < 4; c++) {
        cpa_wait1();
        __syncthreads();

        const uint32_t soff = (uint32_t)(c & 1) * 32768;
#pragma unroll
        for (int s = 0; s < 4; s++) {
            const uint32_t offA = (uint32_t)(((2 * s + (g >> 1)) ^ r7) << 4) + soff;
            const uint32_t offB = (uint32_t)(((2 * s + (g & 1)) ^ r7) << 4) + soff;
            uint4 a0 = ldsm4(aA[0] + offA);
            uint4 a1 = ldsm4(aA[1] + offA);
            uint4 a2 = ldsm4(aA[2] + offA);
            uint4 a3 = ldsm4(aA[3] + offA);
            uint4 b0 = ldsm4(aB[0] + offB);
            uint4 b1 = ldsm4(aB[1] + offB);
            mma_f16(acc[0][0], a0, b0.x, b0.y);
            mma_f16(acc[0][1], a0, b0.z, b0.w);
            mma_f16(acc[0][2], a0, b1.x, b1.y);
            mma_f16(acc[0][3], a0, b1.z, b1.w);
            mma_f16(acc[1][0], a1, b0.x, b0.y);
            mma_f16(acc[1][1], a1, b0.z, b0.w);
            mma_f16(acc[1][2], a1, b1.x, b1.y);
            mma_f16(acc[1][3], a1, b1.z, b1.w);
            mma_f16(acc[2][0], a2, b0.x, b0.y);
            mma_f16(acc[2][1], a2, b0.z, b0.w);
            mma_f16(acc[2][2], a2, b1.x, b1.y);
            mma_f16(acc[2][3], a2, b1.z, b1.w);
            mma_f16(acc[3][0], a3, b0.x, b0.y);
            mma_f16(acc[3][1], a3, b0.z, b0.w);
            mma_f16(acc[3][2], a3, b1.x, b1.y);
            mma_f16(acc[3][3], a3, b1.z, b1.w);
        }
        __syncthreads();

        if (c + 2 < 4)
            stage_chunk_h(Ah, Wh, m0, n0, c + 2,
                          sb + (uint32_t)(c & 1) * 32768, tid);
        cpa_commit();
    }

#pragma unroll
    for (int t = 0; t < 4; t++) {
#pragma unroll
        for (int nb = 0; nb < 4; nb++) {
            int r = m0 + wm + t * 16 + qr;
            int cc = n0 + wn + nb * 8 + qc * 2;
            float b0 = bias[cc], b1 = bias[cc + 1];
            if (HEAD_OUT) {
                // head-blocked fp16: ((which*8+h)*MROWS + r)*32 + d
                int which = cc >> 8, hh = (cc >> 5) & 7, dd = cc & 31;
                float sc = (which == 0) ? QSCALE : 1.f;
                __half* Oh = (__half*)OutP;
                size_t base = (size_t)(which * 8 + hh) * MROWS * 32 + dd;
                *reinterpret_cast<uint32_t*>(&Oh[base + (size_t)r * 32]) =
                    f2h2((acc[t][nb][0] + b0) * sc, (acc[t][nb][1] + b1) * sc);
                *reinterpret_cast<uint32_t*>(&Oh[base + (size_t)(r + 8) * 32]) =
                    f2h2((acc[t][nb][2] + b0) * sc, (acc[t][nb][3] + b1) * sc);
            } else {
                float* Of = (float*)OutP;
                *reinterpret_cast<float2*>(&Of[(size_t)r * N + cc]) =
                    make_float2(acc[t][nb][0] + b0, acc[t][nb][1] + b1);
                *reinterpret_cast<float2*>(&Of[(size_t)(r + 8) * N + cc]) =
                    make_float2(acc[t][nb][2] + b0, acc[t][nb][3] + b1);
            }
        }
    }
}

__global__ void __launch_bounds__(256, 2) qkv_gemm_kernel(
    const float* __restrict__ qkv_b)
{
    gemm_f16_body<true>(g_xh, g_wqkvh, qkv_b, g_qkvh, N3);
}

__global__ void __launch_bounds__(256, 2) out_gemm_kernel(
    const float* __restrict__ out_b, float* __restrict__ out)
{
    gemm_f16_body<false>(g_ctxh, g_wouth, out_b, out, CDIM);
}

// ---------------------------------------------------------------------------
// fp16 window attention. CTA = 256 threads = 8 warps = 1 window; warp = head.
// Per-warp smem: Q[64][32h] | K | V, 4KB each; rows 64B, 4-slot XOR swizzle.
// Coalesced cp.async staging (head-blocked qkv). Bias table (m-dim 64)
// initializes the S accumulators; pad cols/rows = -60000.
// ---------------------------------------------------------------------------
#define WBYTES 12288
#define SMEM_ATTN (8 * WBYTES)    // 98304

__global__ void __launch_bounds__(256, 2) win_attn_kernel()
{
    extern __shared__ __align__(16) char smem[];

    const int w    = blockIdx.x;
    const int tid  = threadIdx.x;
    const int lane = tid & 31;
    const int h    = tid >> 5;        // warp == head
    const int qr   = lane >> 2, qc = lane & 3;
    const int g    = lane >> 3, r7 = lane & 7;

    char* wbuf = smem + h * WBYTES;
    const uint32_t qb = s2u(wbuf);
    const uint32_t kb = qb + 4096;
    const uint32_t vb = qb + 8192;

    // ---- zero pad rows 49..63 of Q, K, V (K must be 0: bias is ADDED) ----
    {
        uint4 z = make_uint4(0, 0, 0, 0);
        for (int i = lane; i < 180; i += 32) {
            int b = i / 60, j = i - b * 60;
            *reinterpret_cast<uint4*>(wbuf + b * 4096 + 3136 + j * 16) = z;
        }
    }

    // ---- coalesced staging of Q, K, V (3136 B contiguous each) ----
    {
        const size_t gm = (size_t)w * NTOK * 32;
        const __half* srcQ = g_qkvh + (size_t)h        * MROWS * 32 + gm;
        const __half* srcK = g_qkvh + (size_t)(8 + h)  * MROWS * 32 + gm;
        const __half* srcV = g_qkvh + (size_t)(16 + h) * MROWS * 32 + gm;
        for (int i = lane; i < 196; i += 32) {
            int row = i >> 2, slot = i & 3;
            uint32_t doff = row * 64 + ((slot ^ ((row >> 1) & 3)) << 4);
            cpa16(qb + doff, srcQ + i * 8);
            cpa16(kb + doff, srcK + i * 8);
            cpa16(vb + doff, srcV + i * 8);
        }
        cpa_commit();
        cpa_wait0();
        __syncwarp();
    }

    const __half* bmh = g_bm + ((size_t)(w & 63) * 8 + h) * 4096;

#pragma unroll 1
    for (int half = 0; half < 2; half++) {
        const int mb = half * 32;

        // ---- init S accumulators from fused bias table (row stride 64) ----
        float acc[2][8][4];
#pragma unroll
        for (int mt = 0; mt < 2; mt++) {
            int r0 = mb + mt * 16 + qr;
#pragma unroll
            for (int nt = 0; nt < 8; nt++) {
                int m0 = nt * 8 + 2 * qc;
                __half2 b0 = *reinterpret_cast<const __half2*>(&bmh[r0 * 64 + m0]);
                __half2 b1 = *reinterpret_cast<const __half2*>(&bmh[(r0 + 8) * 64 + m0]);
                float2 f0 = __half22float2(b0);
                float2 f1 = __half22float2(b1);
                acc[mt][nt][0] = f0.x; acc[mt][nt][1] = f0.y;
                acc[mt][nt][2] = f1.x; acc[mt][nt][3] = f1.y;
            }
        }

        // ---- S = Q K^T + bias ----
#pragma unroll
        for (int s = 0; s < 2; s++) {
            uint4 af[2];
#pragma unroll
            for (int mt = 0; mt < 2; mt++) {
                int row  = mb + mt * 16 + (g & 1) * 8 + r7;
                int slot = 2 * s + (g >> 1);
                af[mt] = ldsm4(qb + row * 64 + ((slot ^ ((row >> 1) & 3)) << 4));
            }
#pragma unroll
            for (int p = 0; p < 4; p++) {
                int row  = p * 16 + (g >> 1) * 8 + r7;
                int slot = 2 * s + (g & 1);
                uint4 bb = ldsm4(kb + row * 64 + ((slot ^ ((row >> 1) & 3)) << 4));
#pragma unroll
                for (int mt = 0; mt < 2; mt++) {
                    mma_f16(acc[mt][2 * p],     af[mt], bb.x, bb.y);
                    mma_f16(acc[mt][2 * p + 1], af[mt], bb.z, bb.w);
                }
            }
        }

        // ---- softmax (rows spread over quad lanes) ----
#pragma unroll
        for (int mt = 0; mt < 2; mt++) {
            float mx0 = -1e30f, mx1 = -1e30f;
#pragma unroll
            for (int nt = 0; nt < 8; nt++) {
                mx0 = fmaxf(mx0, fmaxf(acc[mt][nt][0], acc[mt][nt][1]));
                mx1 = fmaxf(mx1, fmaxf(acc[mt][nt][2], acc[mt][nt][3]));
            }
#pragma unroll
            for (int o = 1; o < 4; o <<= 1) {
                mx0 = fmaxf(mx0, __shfl_xor_sync(0xffffffffu, mx0, o));
                mx1 = fmaxf(mx1, __shfl_xor_sync(0xffffffffu, mx1, o));
            }
            float s0 = 0.f, s1 = 0.f;
#pragma unroll
            for (int nt = 0; nt < 8; nt++) {
                acc[mt][nt][0] = __expf(acc[mt][nt][0] - mx0);
                acc[mt][nt][1] = __expf(acc[mt][nt][1] - mx0);
                acc[mt][nt][2] = __expf(acc[mt][nt][2] - mx1);
                acc[mt][nt][3] = __expf(acc[mt][nt][3] - mx1);
                s0 += acc[mt][nt][0] + acc[mt][nt][1];
                s1 += acc[mt][nt][2] + acc[mt][nt][3];
            }
#pragma unroll
            for (int o = 1; o < 4; o <<= 1) {
                s0 += __shfl_xor_sync(0xffffffffu, s0, o);
                s1 += __shfl_xor_sync(0xffffffffu, s1, o);
            }
            float i0 = 1.f / s0, i1 = 1.f / s1;
#pragma unroll
            for (int nt = 0; nt < 8; nt++) {
                acc[mt][nt][0] *= i0; acc[mt][nt][1] *= i0;
                acc[mt][nt][2] *= i1; acc[mt][nt][3] *= i1;
            }
        }

        // ---- C = P V ----
        float cacc[2][4][4];
#pragma unroll
        for (int mt = 0; mt < 2; mt++)
#pragma unroll
            for (int dt = 0; dt < 4; dt++)
#pragma unroll
                for (int j = 0; j < 4; j++) cacc[mt][dt][j] = 0.f;

#pragma unroll
        for (int j = 0; j < 4; j++) {
            uint4 aP[2];
#pragma unroll
            for (int mt = 0; mt < 2; mt++) {
                aP[mt].x = f2h2(acc[mt][2 * j][0],     acc[mt][2 * j][1]);
                aP[mt].y = f2h2(acc[mt][2 * j][2],     acc[mt][2 * j][3]);
                aP[mt].z = f2h2(acc[mt][2 * j + 1][0], acc[mt][2 * j + 1][1]);
                aP[mt].w = f2h2(acc[mt][2 * j + 1][2], acc[mt][2 * j + 1][3]);
            }
#pragma unroll
            for (int dp = 0; dp < 2; dp++) {
                int row  = 16 * j + (g & 1) * 8 + r7;
                int slot = 2 * dp + (g >> 1);
                uint4 bb = ldsm4t(vb + row * 64 + ((slot ^ ((row >> 1) & 3)) << 4));
#pragma unroll
                for (int mt = 0; mt < 2; mt++) {
                    mma_f16(cacc[mt][2 * dp],     aP[mt], bb.x, bb.y);
                    mma_f16(cacc[mt][2 * dp + 1], aP[mt], bb.z, bb.w);
                }
            }
        }

        // ---- store ctx (fp16, standard (M,256) layout for out GEMM) ----
#pragma unroll
        for (int mt = 0; mt < 2; mt++) {
            int n0 = mb + mt * 16 + qr;
#pragma unroll
            for (int dt = 0; dt < 4; dt++) {
                int col = h * HD + dt * 8 + 2 * qc;
                if (n0 < NTOK)
                    *reinterpret_cast<uint32_t*>(
                        &g_ctxh[((size_t)w * NTOK + n0) * CDIM + col]) =
                        f2h2(cacc[mt][dt][0], cacc[mt][dt][1]);
                if (n0 + 8 < NTOK)
                    *reinterpret_cast<uint32_t*>(
                        &g_ctxh[((size_t)w * NTOK + n0 + 8) * CDIM + col]) =
                        f2h2(cacc[mt][dt][2], cacc[mt][dt][3]);
            }
        }
    }
}

// ---------------------------------------------------------------------------
extern "C" void kernel_launch(void* const* d_in, const int* in_sizes, int n_in,
                              void* d_out, int out_size)
{
    const float* x     = (const float*)d_in[0];
    const float* mask  = (const float*)d_in[1];
    const float* qkv_w = (const float*)d_in[2];
    const float* qkv_b = (const float*)d_in[3];
    const float* rpe   = (const float*)d_in[4];
    const float* out_w = (const float*)d_in[5];
    const float* out_b = (const float*)d_in[6];
    const int*   rel   = (const int*)d_in[7];
    float* out = (float*)d_out;

    cudaFuncSetAttribute(win_attn_kernel,
                         cudaFuncAttributeMaxDynamicSharedMemorySize, SMEM_ATTN);

    cvt_x_kernel<<<(MROWS * CDIM / 4) / 256, 256>>>(x);
    cvt_w_kernel<<<((N3 * CDIM + CDIM * CDIM) / 4) / 256, 256>>>(qkv_w, out_w);
    build_bm_kernel<<<(64 * 8 * 64 * 64) / 256, 256>>>(mask, rpe, rel);

    dim3 g1(N3 / 128, MROWS / 128);   // 6 x 1568
    qkv_gemm_kernel<<<g1, 256>>>(qkv_b);

    win_attn_kernel<<<NWIN, 256, SMEM_ATTN>>>();

    dim3 g3(CDIM / 128, MROWS / 128); // 2 x 1568
    out_gemm_kernel<<<g3, 256>>>(out_b, out);
}

// round 11
// speedup vs baseline: 7.1213x; 1.0688x over previous
#include <cuda_runtime.h>
#include <cuda_fp16.h>
#include <cstdint>

// ---------------------------------------------------------------------------
// ShiftedWindowAttention (Swin window-MSA) — all-fp16 tensor-core pipeline
//   Stage 0: x / weights -> fp16; fused (mask + rpe-bias) table build
//   Stage 1: qkv GEMM (fp16 in/out, head-blocked output, q pre-scaled),
//            3-stage cp.async pipeline, one barrier per K-chunk
//   Stage 2: window attention, warp = (window, head)
//   Stage 3: out GEMM (same pipelined body, fp32 out)
// ---------------------------------------------------------------------------

#define NWIN    4096
#define NTOK    49
#define CDIM    256
#define HEADS_N 8
#define HD      32
#define MROWS   (NWIN * NTOK)    // 200704
#define N3      (3 * CDIM)       // 768
#define QSCALE  0.1767766952966369f

// qkv head-blocked: addr = ((which*8 + h)*MROWS + m)*32 + d
__device__ __half g_qkvh[(size_t)MROWS * N3];
__device__ __half g_xh[(size_t)MROWS * CDIM];
__device__ __half g_ctxh[(size_t)MROWS * CDIM];
__device__ __half g_wqkvh[N3 * CDIM];
__device__ __half g_wouth[CDIM * CDIM];
// fused bias+mask table: [wm 64][h 8][n 64][m 64], pad = -60000
__device__ __align__(16) __half g_bm[64 * 8 * 64 * 64];

// ---------------------------------------------------------------------------
// helpers
// ---------------------------------------------------------------------------
__device__ __forceinline__ uint32_t f2h2(float lo, float hi) {
    uint32_t u;
    asm("cvt.rn.f16x2.f32 %0, %1, %2;" : "=r"(u) : "f"(hi), "f"(lo));
    return u;
}

__device__ __forceinline__ uint32_t s2u(const void* p) {
    return (uint32_t)__cvta_generic_to_shared(p);
}

__device__ __forceinline__ uint4 ldsm4(uint32_t a) {
    uint4 r;
    asm volatile("ldmatrix.sync.aligned.m8n8.x4.shared.b16 {%0,%1,%2,%3}, [%4];"
                 : "=r"(r.x), "=r"(r.y), "=r"(r.z), "=r"(r.w) : "r"(a));
    return r;
}

__device__ __forceinline__ uint4 ldsm4t(uint32_t a) {
    uint4 r;
    asm volatile("ldmatrix.sync.aligned.m8n8.x4.trans.shared.b16 {%0,%1,%2,%3}, [%4];"
                 : "=r"(r.x), "=r"(r.y), "=r"(r.z), "=r"(r.w) : "r"(a));
    return r;
}

__device__ __forceinline__ void cpa16(uint32_t dst, const void* src) {
    asm volatile("cp.async.cg.shared.global [%0], [%1], 16;"
                 :: "r"(dst), "l"(src));
}
__device__ __forceinline__ void cpa_commit() {
    asm volatile("cp.async.commit_group;");
}
__device__ __forceinline__ void cpa_wait1() {
    asm volatile("cp.async.wait_group 1;");
}
__device__ __forceinline__ void cpa_wait0() {
    asm volatile("cp.async.wait_group 0;");
}

__device__ __forceinline__ void mma_f16(float* c, const uint4& a,
                                        unsigned b0, unsigned b1) {
    asm volatile(
        "mma.sync.aligned.m16n8k16.row.col.f32.f16.f16.f32 "
        "{%0,%1,%2,%3}, {%4,%5,%6,%7}, {%8,%9}, {%0,%1,%2,%3};"
        : "+f"(c[0]), "+f"(c[1]), "+f"(c[2]), "+f"(c[3])
        : "r"(a.x), "r"(a.y), "r"(a.z), "r"(a.w), "r"(b0), "r"(b1));
}

// ---------------------------------------------------------------------------
// prepass kernels
// ---------------------------------------------------------------------------
__global__ void __launch_bounds__(256) cvt_x_kernel(const float* __restrict__ x)
{
    int i = blockIdx.x * 256 + threadIdx.x;
    float4 v = reinterpret_cast<const float4*>(x)[i];
    reinterpret_cast<uint2*>(g_xh)[i] =
        make_uint2(f2h2(v.x, v.y), f2h2(v.z, v.w));
}

__global__ void __launch_bounds__(256) cvt_w_kernel(
    const float* __restrict__ qkv_w, const float* __restrict__ out_w)
{
    int i = blockIdx.x * 256 + threadIdx.x;
    if (i < (N3 * CDIM) / 4) {
        float4 v = reinterpret_cast<const float4*>(qkv_w)[i];
        reinterpret_cast<uint2*>(g_wqkvh)[i] =
            make_uint2(f2h2(v.x, v.y), f2h2(v.z, v.w));
    } else {
        int j = i - (N3 * CDIM) / 4;
        float4 v = reinterpret_cast<const float4*>(out_w)[j];
        reinterpret_cast<uint2*>(g_wouth)[j] =
            make_uint2(f2h2(v.x, v.y), f2h2(v.z, v.w));
    }
}

// fused bias table: bm[wm][h][n][m] = mask(wm,n,m) + rpe[rel(n,m)][h], pad -6e4
__global__ void __launch_bounds__(256) build_bm_kernel(
    const float* __restrict__ mask, const float* __restrict__ rpe,
    const int* __restrict__ rel_index)
{
    int idx = blockIdx.x * 256 + threadIdx.x;   // 64*8*64*64 total
    int m  = idx & 63;
    int n  = (idx >> 6) & 63;
    int h  = (idx >> 12) & 7;
    int wm = idx >> 15;
    float v = -60000.f;
    if (n < NTOK && m < NTOK) {
        int nm = n * NTOK + m;
        v = mask[wm * NTOK * NTOK + nm] + rpe[rel_index[nm] * HEADS_N + h];
    }
    g_bm[idx] = __float2half(v);
}

// ---------------------------------------------------------------------------
// fp16 GEMM:  Out[m,n] = sum_k A[m,k] * W[n,k] + bias[n]   (K = 256)
// Block 128x128, 8 warps (2m x 4n), warp tile 64x32, chunk = 64 halves,
// THREE-stage cp.async pipeline, ONE __syncthreads per chunk:
//   iter c: wait_group(1); barrier; stage chunk c+2 -> buf (c+2)%3; commit;
//           mma on buf c%3.
// Barrier proves all warps finished reads of buf (c-1)%3 == (c+2)%3.
// ---------------------------------------------------------------------------
#define GEMM_SMEM 98304   // 3 stages x (A 16KB + W 16KB)

__device__ __forceinline__ void stage_chunk_h(
    const __half* __restrict__ Ah, const __half* __restrict__ Wh,
    int m0, int n0, int c, uint32_t dstbase, int tid)
{
    const int rr   = tid >> 1;
    const int segb = (tid & 1) * 4;
    const char* As = reinterpret_cast<const char*>(Ah) +
                     (size_t)(m0 + rr) * 512 + c * 128;
    const char* Ws = reinterpret_cast<const char*>(Wh) +
                     (size_t)(n0 + rr) * 512 + c * 128;
    const uint32_t drow = dstbase + rr * 128;
#pragma unroll
    for (int i = 0; i < 4; i++) {
        int seg = segb + i;
        uint32_t d = drow + ((seg ^ (rr & 7)) << 4);
        cpa16(d,         As + seg * 16);
        cpa16(d + 16384, Ws + seg * 16);
    }
}

template <bool HEAD_OUT>
__device__ __forceinline__ void gemm_f16_body(
    const __half* __restrict__ Ah, const __half* __restrict__ Wh,
    const float* __restrict__ bias, void* __restrict__ OutP, int N)
{
    extern __shared__ __align__(16) char sbuf[];

    const int tid  = threadIdx.x;
    const int m0   = blockIdx.y * 128;
    const int n0   = blockIdx.x * 128;
    const int warp = tid >> 5, lane = tid & 31;
    const int qr   = lane >> 2, qc = lane & 3;
    const int wm   = (warp >> 2) * 64;
    const int wn   = (warp & 3) * 32;
    const int g    = lane >> 3, r7 = lane & 7;

    const uint32_t sb = s2u(sbuf);

    uint32_t aA[4], aB[2];
#pragma unroll
    for (int t = 0; t < 4; t++)
        aA[t] = sb + (uint32_t)(wm + 16 * t + (g & 1) * 8 + r7) * 128;
#pragma unroll
    for (int t = 0; t < 2; t++)
        aB[t] = sb + 16384 + (uint32_t)(wn + 16 * t + (g >> 1) * 8 + r7) * 128;

    float acc[4][4][4];
#pragma unroll
    for (int t = 0; t < 4; t++)
#pragma unroll
        for (int nb = 0; nb < 4; nb++)
#pragma unroll
            for (int j = 0; j < 4; j++) acc[t][nb][j] = 0.f;

    // prologue: stage chunks 0,1 into buffers 0,1
    stage_chunk_h(Ah, Wh, m0, n0, 0, sb, tid);
    cpa_commit();
    stage_chunk_h(Ah, Wh, m0, n0, 1, sb + 32768, tid);
    cpa_commit();

#pragma unroll 1
    for (int c = 0; c < 4; c++) {
        cpa_wait1();            // chunk c landed
        __syncthreads();        // all warps done with buf (c-1)%3 == (c+2)%3

        if (c + 2 < 4)
            stage_chunk_h(Ah, Wh, m0, n0, c + 2,
                          sb + (uint32_t)((c + 2) % 3) * 32768, tid);
        cpa_commit();           // uniform group accounting

        const uint32_t soff = (uint32_t)(c % 3) * 32768;
#pragma unroll
        for (int s = 0; s < 4; s++) {
            const uint32_t offA = (uint32_t)(((2 * s + (g >> 1)) ^ r7) << 4) + soff;
            const uint32_t offB = (uint32_t)(((2 * s + (g & 1)) ^ r7) << 4) + soff;
            uint4 a0 = ldsm4(aA[0] + offA);
            uint4 a1 = ldsm4(aA[1] + offA);
            uint4 a2 = ldsm4(aA[2] + offA);
            uint4 a3 = ldsm4(aA[3] + offA);
            uint4 b0 = ldsm4(aB[0] + offB);
            uint4 b1 = ldsm4(aB[1] + offB);
            mma_f16(acc[0][0], a0, b0.x, b0.y);
            mma_f16(acc[0][1], a0, b0.z, b0.w);
            mma_f16(acc[0][2], a0, b1.x, b1.y);
            mma_f16(acc[0][3], a0, b1.z, b1.w);
            mma_f16(acc[1][0], a1, b0.x, b0.y);
            mma_f16(acc[1][1], a1, b0.z, b0.w);
            mma_f16(acc[1][2], a1, b1.x, b1.y);
            mma_f16(acc[1][3], a1, b1.z, b1.w);
            mma_f16(acc[2][0], a2, b0.x, b0.y);
            mma_f16(acc[2][1], a2, b0.z, b0.w);
            mma_f16(acc[2][2], a2, b1.x, b1.y);
            mma_f16(acc[2][3], a2, b1.z, b1.w);
            mma_f16(acc[3][0], a3, b0.x, b0.y);
            mma_f16(acc[3][1], a3, b0.z, b0.w);
            mma_f16(acc[3][2], a3, b1.x, b1.y);
            mma_f16(acc[3][3], a3, b1.z, b1.w);
        }
    }

#pragma unroll
    for (int t = 0; t < 4; t++) {
#pragma unroll
        for (int nb = 0; nb < 4; nb++) {
            int r = m0 + wm + t * 16 + qr;
            int cc = n0 + wn + nb * 8 + qc * 2;
            float b0 = bias[cc], b1 = bias[cc + 1];
            if (HEAD_OUT) {
                // head-blocked fp16: ((which*8+h)*MROWS + r)*32 + d
                int which = cc >> 8, hh = (cc >> 5) & 7, dd = cc & 31;
                float sc = (which == 0) ? QSCALE : 1.f;
                __half* Oh = (__half*)OutP;
                size_t base = (size_t)(which * 8 + hh) * MROWS * 32 + dd;
                *reinterpret_cast<uint32_t*>(&Oh[base + (size_t)r * 32]) =
                    f2h2((acc[t][nb][0] + b0) * sc, (acc[t][nb][1] + b1) * sc);
                *reinterpret_cast<uint32_t*>(&Oh[base + (size_t)(r + 8) * 32]) =
                    f2h2((acc[t][nb][2] + b0) * sc, (acc[t][nb][3] + b1) * sc);
            } else {
                float* Of = (float*)OutP;
                *reinterpret_cast<float2*>(&Of[(size_t)r * N + cc]) =
                    make_float2(acc[t][nb][0] + b0, acc[t][nb][1] + b1);
                *reinterpret_cast<float2*>(&Of[(size_t)(r + 8) * N + cc]) =
                    make_float2(acc[t][nb][2] + b0, acc[t][nb][3] + b1);
            }
        }
    }
}

__global__ void __launch_bounds__(256, 2) qkv_gemm_kernel(
    const float* __restrict__ qkv_b)
{
    gemm_f16_body<true>(g_xh, g_wqkvh, qkv_b, g_qkvh, N3);
}

__global__ void __launch_bounds__(256, 2) out_gemm_kernel(
    const float* __restrict__ out_b, float* __restrict__ out)
{
    gemm_f16_body<false>(g_ctxh, g_wouth, out_b, out, CDIM);
}

// ---------------------------------------------------------------------------
// fp16 window attention (unchanged from R10).
// ---------------------------------------------------------------------------
#define WBYTES 12288
#define SMEM_ATTN (8 * WBYTES)    // 98304

__global__ void __launch_bounds__(256, 2) win_attn_kernel()
{
    extern __shared__ __align__(16) char smem[];

    const int w    = blockIdx.x;
    const int tid  = threadIdx.x;
    const int lane = tid & 31;
    const int h    = tid >> 5;        // warp == head
    const int qr   = lane >> 2, qc = lane & 3;
    const int g    = lane >> 3, r7 = lane & 7;

    char* wbuf = smem + h * WBYTES;
    const uint32_t qb = s2u(wbuf);
    const uint32_t kb = qb + 4096;
    const uint32_t vb = qb + 8192;

    // ---- zero pad rows 49..63 of Q, K, V ----
    {
        uint4 z = make_uint4(0, 0, 0, 0);
        for (int i = lane; i < 180; i += 32) {
            int b = i / 60, j = i - b * 60;
            *reinterpret_cast<uint4*>(wbuf + b * 4096 + 3136 + j * 16) = z;
        }
    }

    // ---- coalesced staging of Q, K, V (3136 B contiguous each) ----
    {
        const size_t gm = (size_t)w * NTOK * 32;
        const __half* srcQ = g_qkvh + (size_t)h        * MROWS * 32 + gm;
        const __half* srcK = g_qkvh + (size_t)(8 + h)  * MROWS * 32 + gm;
        const __half* srcV = g_qkvh + (size_t)(16 + h) * MROWS * 32 + gm;
        for (int i = lane; i < 196; i += 32) {
            int row = i >> 2, slot = i & 3;
            uint32_t doff = row * 64 + ((slot ^ ((row >> 1) & 3)) << 4);
            cpa16(qb + doff, srcQ + i * 8);
            cpa16(kb + doff, srcK + i * 8);
            cpa16(vb + doff, srcV + i * 8);
        }
        cpa_commit();
        cpa_wait0();
        __syncwarp();
    }

    const __half* bmh = g_bm + ((size_t)(w & 63) * 8 + h) * 4096;

#pragma unroll 1
    for (int half = 0; half < 2; half++) {
        const int mb = half * 32;

        // ---- init S accumulators from fused bias table (row stride 64) ----
        float acc[2][8][4];
#pragma unroll
        for (int mt = 0; mt < 2; mt++) {
            int r0 = mb + mt * 16 + qr;
#pragma unroll
            for (int nt = 0; nt < 8; nt++) {
                int m0 = nt * 8 + 2 * qc;
                __half2 b0 = *reinterpret_cast<const __half2*>(&bmh[r0 * 64 + m0]);
                __half2 b1 = *reinterpret_cast<const __half2*>(&bmh[(r0 + 8) * 64 + m0]);
                float2 f0 = __half22float2(b0);
                float2 f1 = __half22float2(b1);
                acc[mt][nt][0] = f0.x; acc[mt][nt][1] = f0.y;
                acc[mt][nt][2] = f1.x; acc[mt][nt][3] = f1.y;
            }
        }

        // ---- S = Q K^T + bias ----
#pragma unroll
        for (int s = 0; s < 2; s++) {
            uint4 af[2];
#pragma unroll
            for (int mt = 0; mt < 2; mt++) {
                int row  = mb + mt * 16 + (g & 1) * 8 + r7;
                int slot = 2 * s + (g >> 1);
                af[mt] = ldsm4(qb + row * 64 + ((slot ^ ((row >> 1) & 3)) << 4));
            }
#pragma unroll
            for (int p = 0; p < 4; p++) {
                int row  = p * 16 + (g >> 1) * 8 + r7;
                int slot = 2 * s + (g & 1);
                uint4 bb = ldsm4(kb + row * 64 + ((slot ^ ((row >> 1) & 3)) << 4));
#pragma unroll
                for (int mt = 0; mt < 2; mt++) {
                    mma_f16(acc[mt][2 * p],     af[mt], bb.x, bb.y);
                    mma_f16(acc[mt][2 * p + 1], af[mt], bb.z, bb.w);
                }
            }
        }

        // ---- softmax (rows spread over quad lanes) ----
#pragma unroll
        for (int mt = 0; mt < 2; mt++) {
            float mx0 = -1e30f, mx1 = -1e30f;
#pragma unroll
            for (int nt = 0; nt < 8; nt++) {
                mx0 = fmaxf(mx0, fmaxf(acc[mt][nt][0], acc[mt][nt][1]));
                mx1 = fmaxf(mx1, fmaxf(acc[mt][nt][2], acc[mt][nt][3]));
            }
#pragma unroll
            for (int o = 1; o < 4; o <<= 1) {
                mx0 = fmaxf(mx0, __shfl_xor_sync(0xffffffffu, mx0, o));
                mx1 = fmaxf(mx1, __shfl_xor_sync(0xffffffffu, mx1, o));
            }
            float s0 = 0.f, s1 = 0.f;
#pragma unroll
            for (int nt = 0; nt < 8; nt++) {
                acc[mt][nt][0] = __expf(acc[mt][nt][0] - mx0);
                acc[mt][nt][1] = __expf(acc[mt][nt][1] - mx0);
                acc[mt][nt][2] = __expf(acc[mt][nt][2] - mx1);
                acc[mt][nt][3] = __expf(acc[mt][nt][3] - mx1);
                s0 += acc[mt][nt][0] + acc[mt][nt][1];
                s1 += acc[mt][nt][2] + acc[mt][nt][3];
            }
#pragma unroll
            for (int o = 1; o < 4; o <<= 1) {
                s0 += __shfl_xor_sync(0xffffffffu, s0, o);
                s1 += __shfl_xor_sync(0xffffffffu, s1, o);
            }
            float i0 = 1.f / s0, i1 = 1.f / s1;
#pragma unroll
            for (int nt = 0; nt < 8; nt++) {
                acc[mt][nt][0] *= i0; acc[mt][nt][1] *= i0;
                acc[mt][nt][2] *= i1; acc[mt][nt][3] *= i1;
            }
        }

        // ---- C = P V ----
        float cacc[2][4][4];
#pragma unroll
        for (int mt = 0; mt < 2; mt++)
#pragma unroll
            for (int dt = 0; dt < 4; dt++)
#pragma unroll
                for (int j = 0; j < 4; j++) cacc[mt][dt][j] = 0.f;

#pragma unroll
        for (int j = 0; j < 4; j++) {
            uint4 aP[2];
#pragma unroll
            for (int mt = 0; mt < 2; mt++) {
                aP[mt].x = f2h2(acc[mt][2 * j][0],     acc[mt][2 * j][1]);
                aP[mt].y = f2h2(acc[mt][2 * j][2],     acc[mt][2 * j][3]);
                aP[mt].z = f2h2(acc[mt][2 * j + 1][0], acc[mt][2 * j + 1][1]);
                aP[mt].w = f2h2(acc[mt][2 * j + 1][2], acc[mt][2 * j + 1][3]);
            }
#pragma unroll
            for (int dp = 0; dp < 2; dp++) {
                int row  = 16 * j + (g & 1) * 8 + r7;
                int slot = 2 * dp + (g >> 1);
                uint4 bb = ldsm4t(vb + row * 64 + ((slot ^ ((row >> 1) & 3)) << 4));
#pragma unroll
                for (int mt = 0; mt < 2; mt++) {
                    mma_f16(cacc[mt][2 * dp],     aP[mt], bb.x, bb.y);
                    mma_f16(cacc[mt][2 * dp + 1], aP[mt], bb.z, bb.w);
                }
            }
        }

        // ---- store ctx (fp16, standard (M,256) layout for out GEMM) ----
#pragma unroll
        for (int mt = 0; mt < 2; mt++) {
            int n0 = mb + mt * 16 + qr;
#pragma unroll
            for (int dt = 0; dt < 4; dt++) {
                int col = h * HD + dt * 8 + 2 * qc;
                if (n0 < NTOK)
                    *reinterpret_cast<uint32_t*>(
                        &g_ctxh[((size_t)w * NTOK + n0) * CDIM + col]) =
                        f2h2(cacc[mt][dt][0], cacc[mt][dt][1]);
                if (n0 + 8 < NTOK)
                    *reinterpret_cast<uint32_t*>(
                        &g_ctxh[((size_t)w * NTOK + n0 + 8) * CDIM + col]) =
                        f2h2(cacc[mt][dt][2], cacc[mt][dt][3]);
            }
        }
    }
}

// ---------------------------------------------------------------------------
extern "C" void kernel_launch(void* const* d_in, const int* in_sizes, int n_in,
                              void* d_out, int out_size)
{
    const float* x     = (const float*)d_in[0];
    const float* mask  = (const float*)d_in[1];
    const float* qkv_w = (const float*)d_in[2];
    const float* qkv_b = (const float*)d_in[3];
    const float* rpe   = (const float*)d_in[4];
    const float* out_w = (const float*)d_in[5];
    const float* out_b = (const float*)d_in[6];
    const int*   rel   = (const int*)d_in[7];
    float* out = (float*)d_out;

    cudaFuncSetAttribute(win_attn_kernel,
                         cudaFuncAttributeMaxDynamicSharedMemorySize, SMEM_ATTN);
    cudaFuncSetAttribute(qkv_gemm_kernel,
                         cudaFuncAttributeMaxDynamicSharedMemorySize, GEMM_SMEM);
    cudaFuncSetAttribute(out_gemm_kernel,
                         cudaFuncAttributeMaxDynamicSharedMemorySize, GEMM_SMEM);

    cvt_x_kernel<<<(MROWS * CDIM / 4) / 256, 256>>>(x);
    cvt_w_kernel<<<((N3 * CDIM + CDIM * CDIM) / 4) / 256, 256>>>(qkv_w, out_w);
    build_bm_kernel<<<(64 * 8 * 64 * 64) / 256, 256>>>(mask, rpe, rel);

    dim3 g1(N3 / 128, MROWS / 128);   // 6 x 1568
    qkv_gemm_kernel<<<g1, 256, GEMM_SMEM>>>(qkv_b);

    win_attn_kernel<<<NWIN, 256, SMEM_ATTN>>>();

    dim3 g3(CDIM / 128, MROWS / 128); // 2 x 1568
    out_gemm_kernel<<<g3, 256, GEMM_SMEM>>>(out_b, out);
}